// round 1
// baseline (speedup 1.0000x reference)
#include <cuda_runtime.h>
#include <math.h>

#define LL 128
#define DD 2048
#define BSZ 32
#define TT 2048
#define NC 20

// ---------------- device scratch (no allocation allowed) ----------------
__device__ float g_S[96 * 16384];     // 0..31 LCS s-mats, 32..63 FSD-M, 64..95 FSD-G
__device__ float g_rn[5 * 4096];      // reciprocal norms: 0 lcs, 1 act-m, 2 act-g, 3 bak-m, 4 bak-g
__device__ float g_bstats[BSZ * 5];   // guide, sparse, ni, nc, nb per batch
__device__ float g_dp[64];            // 0..31 lcs dp results, 32..63 fsd dp results

__device__ __forceinline__ float warpSum(float v) {
    #pragma unroll
    for (int o = 16; o > 0; o >>= 1) v += __shfl_down_sync(0xffffffffu, v, o);
    return v;
}

// ---------------- 1) row norms ----------------
// grid 4096 (= B*L rows), 128 threads
__global__ void norm_kernel(const float* __restrict__ lcs,
                            const float* __restrict__ fa,
                            const float* __restrict__ fb) {
    int r = blockIdx.x;
    int t = threadIdx.x;
    const float4* lrow = (const float4*)(lcs + (size_t)r * DD);
    const float4* arow = (const float4*)(fa  + (size_t)r * DD);
    const float4* brow = (const float4*)(fb  + (size_t)r * DD);
    float s_l = 0.f, s_am = 0.f, s_ag = 0.f, s_bm = 0.f, s_bg = 0.f;
    for (int q = t; q < 512; q += 128) {
        float4 v = lrow[q];
        s_l += v.x*v.x + v.y*v.y + v.z*v.z + v.w*v.w;
        float4 a = arow[q];
        float sa = a.x*a.x + a.y*a.y + a.z*a.z + a.w*a.w;
        float4 b = brow[q];
        float sb = b.x*b.x + b.y*b.y + b.z*b.z + b.w*b.w;
        if (q < 256) { s_am += sa; s_bm += sb; }
        else         { s_ag += sa; s_bg += sb; }
    }
    __shared__ float red[5][4];
    float vals[5] = {s_l, s_am, s_ag, s_bm, s_bg};
    int w = t >> 5, lane = t & 31;
    #pragma unroll
    for (int k = 0; k < 5; k++) {
        float s = warpSum(vals[k]);
        if (lane == 0) red[k][w] = s;
    }
    __syncthreads();
    if (t == 0) {
        #pragma unroll
        for (int k = 0; k < 5; k++) {
            float s = red[k][0] + red[k][1] + red[k][2] + red[k][3];
            g_rn[k * 4096 + r] = 1.0f / sqrtf(s);
        }
    }
}

// ---------------- 2) per-batch stats ----------------
// grid 32, 256 threads
__global__ void bstats_kernel(const float* __restrict__ att,
                              const float* __restrict__ cas,
                              const float* __restrict__ fi,
                              const float* __restrict__ fc,
                              const float* __restrict__ fbk) {
    int b = blockIdx.x;
    int t = threadIdx.x;
    float guide = 0.f, sp = 0.f, ni = 0.f, nc = 0.f, nb = 0.f;
    for (int q = t; q < TT; q += 256) {
        float c  = cas[((size_t)b * TT + q) * 21 + 20];
        float a0 = att[((size_t)b * TT + q) * 3 + 0];
        float a1 = att[((size_t)b * TT + q) * 3 + 1];
        guide += fabsf(1.0f - c - a0);
        sp += a0 + a1;
    }
    for (int q = t; q < DD; q += 256) {
        float x;
        x = fi [b * DD + q]; ni += x * x;
        x = fc [b * DD + q]; nc += x * x;
        x = fbk[b * DD + q]; nb += x * x;
    }
    __shared__ float red[5][8];
    float vals[5] = {guide, sp, ni, nc, nb};
    int w = t >> 5, lane = t & 31;
    #pragma unroll
    for (int k = 0; k < 5; k++) {
        float s = warpSum(vals[k]);
        if (lane == 0) red[k][w] = s;
    }
    __syncthreads();
    if (t == 0) {
        float s0 = 0, s1 = 0, s2 = 0, s3 = 0, s4 = 0;
        #pragma unroll
        for (int w2 = 0; w2 < 8; w2++) {
            s0 += red[0][w2]; s1 += red[1][w2]; s2 += red[2][w2];
            s3 += red[3][w2]; s4 += red[4][w2];
        }
        g_bstats[b * 5 + 0] = s0;
        g_bstats[b * 5 + 1] = s1;
        g_bstats[b * 5 + 2] = sqrtf(s2);
        g_bstats[b * 5 + 3] = sqrtf(s3);
        g_bstats[b * 5 + 4] = sqrtf(s4);
    }
}

// ---------------- 3) batched pair similarity GEMM ----------------
// grid (2, 2, 96), 256 threads; 64x64 output tile, 4x4 per thread, K-tile 32
__global__ void sim_kernel(const float* __restrict__ lcs,
                           const float* __restrict__ fa,
                           const float* __restrict__ fb,
                           const int* __restrict__ pos,
                           const int* __restrict__ neg) {
    int z = blockIdx.z;
    int job = (z < 32) ? 0 : ((z < 64) ? 1 : 2);   // 0 LCS, 1 FSD-M, 2 FSD-G
    int p = z & 31;
    int ia, ib;
    if (p < 16) { ia = pos[2 * p]; ib = pos[2 * p + 1]; }
    else        { ia = neg[2 * (p - 16)]; ib = neg[2 * (p - 16) + 1]; }

    const float *A, *Bp, *rnA, *rnB;
    int k0, nk;
    if (job == 0) {
        A  = lcs + (size_t)ia * LL * DD;
        Bp = lcs + (size_t)ib * LL * DD;
        rnA = g_rn + 0 * 4096 + ia * LL;
        rnB = g_rn + 0 * 4096 + ib * LL;
        k0 = 0; nk = DD;
    } else {
        int half = job - 1;                  // 0 = first half (M), 1 = second half (G)
        A  = fa + (size_t)ia * LL * DD;
        Bp = ((p < 16) ? fa : fb) + (size_t)ib * LL * DD;
        k0 = half * 1024; nk = 1024;
        rnA = g_rn + (1 + half) * 4096 + ia * LL;
        rnB = g_rn + (((p < 16) ? 1 : 3) + half) * 4096 + ib * LL;
    }
    float* out = g_S + (size_t)z * 16384;

    __shared__ __align__(16) float As[32][68];
    __shared__ __align__(16) float Bs[32][68];

    int tid = threadIdx.x;
    int tn = tid & 15, tm = tid >> 4;
    int i0 = blockIdx.x * 64, j0 = blockIdx.y * 64;

    float acc[4][4];
    #pragma unroll
    for (int r = 0; r < 4; r++)
        #pragma unroll
        for (int c = 0; c < 4; c++) acc[r][c] = 0.f;

    int lrow = tid >> 2;          // 0..63
    int lk = (tid & 3) * 8;       // 0,8,16,24
    const float* Abase = A  + (size_t)(i0 + lrow) * DD + k0 + lk;
    const float* Bbase = Bp + (size_t)(j0 + lrow) * DD + k0 + lk;

    for (int kt = 0; kt < nk; kt += 32) {
        float4 a0 = *(const float4*)(Abase + kt);
        float4 a1 = *(const float4*)(Abase + kt + 4);
        float4 b0 = *(const float4*)(Bbase + kt);
        float4 b1 = *(const float4*)(Bbase + kt + 4);
        __syncthreads();
        As[lk + 0][lrow] = a0.x; As[lk + 1][lrow] = a0.y;
        As[lk + 2][lrow] = a0.z; As[lk + 3][lrow] = a0.w;
        As[lk + 4][lrow] = a1.x; As[lk + 5][lrow] = a1.y;
        As[lk + 6][lrow] = a1.z; As[lk + 7][lrow] = a1.w;
        Bs[lk + 0][lrow] = b0.x; Bs[lk + 1][lrow] = b0.y;
        Bs[lk + 2][lrow] = b0.z; Bs[lk + 3][lrow] = b0.w;
        Bs[lk + 4][lrow] = b1.x; Bs[lk + 5][lrow] = b1.y;
        Bs[lk + 6][lrow] = b1.z; Bs[lk + 7][lrow] = b1.w;
        __syncthreads();
        #pragma unroll
        for (int kk = 0; kk < 32; kk++) {
            float4 av = *(const float4*)&As[kk][tm * 4];
            float4 bv = *(const float4*)&Bs[kk][tn * 4];
            acc[0][0] += av.x * bv.x; acc[0][1] += av.x * bv.y;
            acc[0][2] += av.x * bv.z; acc[0][3] += av.x * bv.w;
            acc[1][0] += av.y * bv.x; acc[1][1] += av.y * bv.y;
            acc[1][2] += av.y * bv.z; acc[1][3] += av.y * bv.w;
            acc[2][0] += av.z * bv.x; acc[2][1] += av.z * bv.y;
            acc[2][2] += av.z * bv.z; acc[2][3] += av.z * bv.w;
            acc[3][0] += av.w * bv.x; acc[3][1] += av.w * bv.y;
            acc[3][2] += av.w * bv.z; acc[3][3] += av.w * bv.w;
        }
    }

    float rA[4], rB[4];
    #pragma unroll
    for (int r = 0; r < 4; r++) rA[r] = rnA[i0 + tm * 4 + r];
    #pragma unroll
    for (int c = 0; c < 4; c++) rB[c] = rnB[j0 + tn * 4 + c];

    #pragma unroll
    for (int r = 0; r < 4; r++)
        #pragma unroll
        for (int c = 0; c < 4; c++) {
            float s = acc[r][c] * rA[r] * rB[c];
            if (job == 0) s = fmaxf(0.f, s - 0.8f) * 5.0f;
            out[(i0 + tm * 4 + r) * 128 + (j0 + tn * 4 + c)] = s;
        }
}

// ---------------- 4) wavefront DP (LCS + FSD fused) ----------------
// grid 64 (0..31 LCS, 32..63 FSD), 128 threads, dynamic smem 132656 B
__global__ void dp_kernel() {
    extern __shared__ float sh[];
    int blk = blockIdx.x;
    int t = threadIdx.x;                  // 0..127
    bool is_fsd = (blk >= 32);
    int p = is_fsd ? (blk - 32) : blk;

    float* M0 = sh;                        // 16384
    float* M1 = sh + 16384;                // 16384 (FSD only)
    float* b0 = sh + 32768;
    float* b1 = b0 + 132;
    float* b2 = b1 + 132;

    if (is_fsd) {
        const float* srcM = g_S + (size_t)(32 + p) * 16384;
        const float* srcG = g_S + (size_t)(64 + p) * 16384;
        for (int q = t; q < 16384; q += 128) { M0[q] = srcM[q]; M1[q] = srcG[q]; }
    } else {
        const float* srcS = g_S + (size_t)p * 16384;
        for (int q = t; q < 16384; q += 128) M0[q] = srcS[q];
    }
    b0[t] = 0.f; b1[t] = 0.f; b2[t] = 0.f;
    if (t == 0) { b0[128] = 0.f; b1[128] = 0.f; b2[128] = 0.f; }
    __syncthreads();

    float* prev2 = b0;
    float* prev1 = b1;
    float* cur   = b2;

    const float GAMMA = 0.1f, INVG = 10.0f;

    for (int d = 2; d <= 256; d++) {
        int j = d - (t + 1);
        float val = 0.f;
        if (j >= 1 && j <= 128) {
            int idx = t * 127 + (d - 2);   // == t*128 + (j-1), stride-127 -> conflict-free
            float cd = prev2[t];
            float cu = prev1[t];
            float cl = prev1[t + 1];
            if (is_fsd) {
                float m = M0[idx];
                float g = M1[idx];
                float a0 = cd, a1 = g + cu, a2 = g + cl;
                float mx = fmaxf(a0, fmaxf(a1, a2));
                float se = expf((a0 - mx) * INVG) + expf((a1 - mx) * INVG)
                         + expf((a2 - mx) * INVG);
                val = m + mx + GAMMA * logf(se);
            } else {
                float s = M0[idx];
                val = (s > 0.5f) ? (cd + s) : fmaxf(cu, cl);
            }
        }
        cur[t + 1] = val;
        __syncthreads();
        float* tmp = prev2; prev2 = prev1; prev1 = cur; cur = tmp;
    }
    if (t == 127) g_dp[blk] = prev1[128];
}

// ---------------- 5) final combine ----------------
// 1 block, 32 threads (one per batch element)
__global__ void final_kernel(const float* __restrict__ xi,
                             const float* __restrict__ xc,
                             const float* __restrict__ xb,
                             const float* __restrict__ vid,
                             float* __restrict__ out) {
    int b = threadIdx.x;  // 0..31
    const float EPS = 1e-45f;

    float s = 0.f;
    for (int c = 0; c < NC; c++) s += vid[b * NC + c];
    float li = 0.f, lcc = 0.f;
    for (int c = 0; c < NC; c++) {
        float v = vid[b * NC + c];
        if (v != 0.f) {
            li  += logf(xi[b * 21 + c] + EPS) * v;
            lcc += logf(xc[b * 21 + c] + EPS) * v;
        }
    }
    lcc += logf(xc[b * 21 + 20] + EPS);          // cont label has 1 in last col
    float lb = logf(xb[b * 21 + 20] + EPS);      // back label = e_last / 1
    float cls_b = -(li / s) - (lcc / (s + 1.0f)) - lb;

    float guide = g_bstats[b * 5 + 0];
    float sp    = g_bstats[b * 5 + 1];
    float ni    = g_bstats[b * 5 + 2];
    float nc2   = g_bstats[b * 5 + 3];
    float nb    = g_bstats[b * 5 + 4];
    float f1 = fmaxf(50.0f - ni + nc2, 0.f);
    float f2 = fmaxf(50.0f - nc2 + nb, 0.f);
    float fsum = f1 + f2 + nb;
    float feat_b = fsum * fsum;

    float lcs_v = g_dp[b];
    float fsd_v = g_dp[32 + b];
    float sign = (b < 16) ? -1.0f : 1.0f;        // loss = (neg mean) - (pos mean)

    float tot = cls_b * (1.0f / 32.0f)
              + 1.0f   * guide  * (1.0f / 32.0f)
              + 5e-5f  * feat_b * (1.0f / 32.0f)
              + 2e-4f  * sp     * (1.0f / 64.0f)          // mean over [B,2]
              + 0.1f * sign * lcs_v * (1.0f / 16.0f)
              + 0.1f * sign * fsd_v * (1.0f / 16.0f);

    tot = warpSum(tot);
    if (b == 0) out[0] = tot;
}

// ---------------- launch ----------------
extern "C" void kernel_launch(void* const* d_in, const int* in_sizes, int n_in,
                              void* d_out, int out_size) {
    const float* xi   = (const float*)d_in[0];
    const float* xc   = (const float*)d_in[1];
    const float* xb   = (const float*)d_in[2];
    const float* vid  = (const float*)d_in[3];
    const float* att  = (const float*)d_in[4];
    const float* fi   = (const float*)d_in[5];
    const float* fc   = (const float*)d_in[6];
    const float* fbk  = (const float*)d_in[7];
    const float* cas  = (const float*)d_in[8];
    const float* lcs  = (const float*)d_in[9];
    const float* fa   = (const float*)d_in[10];
    const float* fb   = (const float*)d_in[11];
    const int*   pos  = (const int*)d_in[12];
    const int*   neg  = (const int*)d_in[13];
    float* out = (float*)d_out;

    const int DP_SMEM = (32768 + 3 * 132) * 4;   // 132656 B
    cudaFuncSetAttribute(dp_kernel, cudaFuncAttributeMaxDynamicSharedMemorySize, DP_SMEM);

    norm_kernel<<<4096, 128>>>(lcs, fa, fb);
    bstats_kernel<<<BSZ, 256>>>(att, cas, fi, fc, fbk);
    dim3 sgrid(2, 2, 96);
    sim_kernel<<<sgrid, 256>>>(lcs, fa, fb, pos, neg);
    dp_kernel<<<64, 128, DP_SMEM>>>();
    final_kernel<<<1, 32>>>(xi, xc, xb, vid, out);
}

// round 2
// speedup vs baseline: 1.5780x; 1.5780x over previous
#include <cuda_runtime.h>
#include <math.h>

#define LL 128
#define DD 2048
#define BSZ 32
#define TT 2048
#define NC 20

// ---------------- device scratch ----------------
// 0..63: LCS raw dot halves (pair p half h at z=2p+h)
// 64..95: FSD-M (normalized), 96..127: FSD-G (normalized)
__device__ float g_S[128 * 16384];
__device__ float g_rn[5 * 4096];     // 0 lcs full, 1 act-m, 2 act-g, 3 bak-m, 4 bak-g
__device__ float g_bstats[BSZ * 5];
__device__ float g_dp[64];

__device__ __forceinline__ float warpSum(float v) {
    #pragma unroll
    for (int o = 16; o > 0; o >>= 1) v += __shfl_down_sync(0xffffffffu, v, o);
    return v;
}

// ---------------- 1) row norms ----------------
__global__ void norm_kernel(const float* __restrict__ lcs,
                            const float* __restrict__ fa,
                            const float* __restrict__ fb) {
    int r = blockIdx.x;
    int t = threadIdx.x;
    const float4* lrow = (const float4*)(lcs + (size_t)r * DD);
    const float4* arow = (const float4*)(fa  + (size_t)r * DD);
    const float4* brow = (const float4*)(fb  + (size_t)r * DD);
    float s_l = 0.f, s_am = 0.f, s_ag = 0.f, s_bm = 0.f, s_bg = 0.f;
    for (int q = t; q < 512; q += 128) {
        float4 v = lrow[q];
        s_l += v.x*v.x + v.y*v.y + v.z*v.z + v.w*v.w;
        float4 a = arow[q];
        float sa = a.x*a.x + a.y*a.y + a.z*a.z + a.w*a.w;
        float4 b = brow[q];
        float sb = b.x*b.x + b.y*b.y + b.z*b.z + b.w*b.w;
        if (q < 256) { s_am += sa; s_bm += sb; }
        else         { s_ag += sa; s_bg += sb; }
    }
    __shared__ float red[5][4];
    float vals[5] = {s_l, s_am, s_ag, s_bm, s_bg};
    int w = t >> 5, lane = t & 31;
    #pragma unroll
    for (int k = 0; k < 5; k++) {
        float s = warpSum(vals[k]);
        if (lane == 0) red[k][w] = s;
    }
    __syncthreads();
    if (t == 0) {
        #pragma unroll
        for (int k = 0; k < 5; k++) {
            float s = red[k][0] + red[k][1] + red[k][2] + red[k][3];
            g_rn[k * 4096 + r] = 1.0f / sqrtf(s);
        }
    }
}

// ---------------- 2) per-batch stats ----------------
__global__ void bstats_kernel(const float* __restrict__ att,
                              const float* __restrict__ cas,
                              const float* __restrict__ fi,
                              const float* __restrict__ fc,
                              const float* __restrict__ fbk) {
    int b = blockIdx.x;
    int t = threadIdx.x;
    float guide = 0.f, sp = 0.f, ni = 0.f, nc = 0.f, nb = 0.f;
    for (int q = t; q < TT; q += 256) {
        float c  = cas[((size_t)b * TT + q) * 21 + 20];
        float a0 = att[((size_t)b * TT + q) * 3 + 0];
        float a1 = att[((size_t)b * TT + q) * 3 + 1];
        guide += fabsf(1.0f - c - a0);
        sp += a0 + a1;
    }
    for (int q = t; q < DD; q += 256) {
        float x;
        x = fi [b * DD + q]; ni += x * x;
        x = fc [b * DD + q]; nc += x * x;
        x = fbk[b * DD + q]; nb += x * x;
    }
    __shared__ float red[5][8];
    float vals[5] = {guide, sp, ni, nc, nb};
    int w = t >> 5, lane = t & 31;
    #pragma unroll
    for (int k = 0; k < 5; k++) {
        float s = warpSum(vals[k]);
        if (lane == 0) red[k][w] = s;
    }
    __syncthreads();
    if (t == 0) {
        float s0=0,s1=0,s2=0,s3=0,s4=0;
        #pragma unroll
        for (int w2 = 0; w2 < 8; w2++) {
            s0 += red[0][w2]; s1 += red[1][w2]; s2 += red[2][w2];
            s3 += red[3][w2]; s4 += red[4][w2];
        }
        g_bstats[b*5+0] = s0;
        g_bstats[b*5+1] = s1;
        g_bstats[b*5+2] = sqrtf(s2);
        g_bstats[b*5+3] = sqrtf(s3);
        g_bstats[b*5+4] = sqrtf(s4);
    }
}

// ---------------- 3) tf32 mma similarity GEMM ----------------
// 128 blocks, 128 threads (4 warps of 64x64), K=1024 each.
// z 0..63: LCS pair p=z>>1, K-half h=z&1, raw dot store.
// z 64..95: FSD-M (first D half), normalized. z 96..127: FSD-G (second half).
#define SIM_STRIDE 36
#define SIM_TILE   (128 * SIM_STRIDE)          // floats per (mat,buf)
#define SIM_SMEM   (4 * SIM_TILE * 4)          // bytes: A0,A1,B0,B1

__device__ __forceinline__ void cp16(float* smem_dst, const float* gsrc) {
    unsigned s = (unsigned)__cvta_generic_to_shared(smem_dst);
    asm volatile("cp.async.cg.shared.global [%0], [%1], 16;\n" :: "r"(s), "l"(gsrc));
}

__global__ void __launch_bounds__(128, 1)
sim_kernel(const float* __restrict__ lcs,
           const float* __restrict__ fa,
           const float* __restrict__ fb,
           const int* __restrict__ pos,
           const int* __restrict__ neg) {
    extern __shared__ float sh[];
    float* Abuf = sh;                 // [2][128][36]
    float* Bbuf = sh + 2 * SIM_TILE;  // [2][128][36]

    int z = blockIdx.x;
    int t = threadIdx.x;
    int w = t >> 5, lane = t & 31;
    int wm = w >> 1, wn = w & 1;
    int lg = lane >> 2, lc = lane & 3;

    int p, koff;
    const float *abase, *bbase, *rA = 0, *rB = 0;
    bool donorm;
    if (z < 64) { p = z >> 1; koff = (z & 1) * 1024; donorm = false; }
    else if (z < 96) { p = z - 64; koff = 0; donorm = true; }
    else { p = z - 96; koff = 1024; donorm = true; }

    int ia, ib;
    if (p < 16) { ia = pos[2*p]; ib = pos[2*p+1]; }
    else        { ia = neg[2*(p-16)]; ib = neg[2*(p-16)+1]; }

    if (z < 64) {
        abase = lcs + (size_t)ia * LL * DD + koff;
        bbase = lcs + (size_t)ib * LL * DD + koff;
    } else {
        int half = (z < 96) ? 0 : 1;
        abase = fa + (size_t)ia * LL * DD + koff;
        bbase = ((p < 16) ? fa : fb) + (size_t)ib * LL * DD + koff;
        rA = g_rn + (1 + half) * 4096 + ia * LL;
        rB = g_rn + (((p < 16) ? 1 : 3) + half) * 4096 + ib * LL;
    }
    float* out = g_S + (size_t)z * 16384;

    float acc[4][8][4];
    #pragma unroll
    for (int mt = 0; mt < 4; mt++)
        #pragma unroll
        for (int nt = 0; nt < 8; nt++)
            #pragma unroll
            for (int j = 0; j < 4; j++) acc[mt][nt][j] = 0.f;

    // prefetch tile 0
    #pragma unroll
    for (int u = 0; u < 8; u++) {
        int fq = u * 128 + t;
        int r = fq >> 3, cq = fq & 7;
        cp16(Abuf + r * SIM_STRIDE + cq * 4, abase + (size_t)r * DD + cq * 4);
        cp16(Bbuf + r * SIM_STRIDE + cq * 4, bbase + (size_t)r * DD + cq * 4);
    }
    asm volatile("cp.async.commit_group;\n");

    int buf = 0;
    for (int it = 0; it < 32; it++) {
        if (it + 1 < 32) {
            float* Ad = Abuf + (buf ^ 1) * SIM_TILE;
            float* Bd = Bbuf + (buf ^ 1) * SIM_TILE;
            int kt = (it + 1) * 32;
            #pragma unroll
            for (int u = 0; u < 8; u++) {
                int fq = u * 128 + t;
                int r = fq >> 3, cq = fq & 7;
                cp16(Ad + r * SIM_STRIDE + cq * 4, abase + (size_t)r * DD + kt + cq * 4);
                cp16(Bd + r * SIM_STRIDE + cq * 4, bbase + (size_t)r * DD + kt + cq * 4);
            }
        }
        asm volatile("cp.async.commit_group;\n");
        asm volatile("cp.async.wait_group 1;\n");
        __syncthreads();

        const float* As = Abuf + buf * SIM_TILE;
        const float* Bs = Bbuf + buf * SIM_TILE;
        #pragma unroll
        for (int ks = 0; ks < 4; ks++) {
            unsigned a[4][4], b[8][2];
            int c0 = ks * 8 + lc;
            #pragma unroll
            for (int mt = 0; mt < 4; mt++) {
                const float* base = As + (wm*64 + mt*16 + lg) * SIM_STRIDE + c0;
                a[mt][0] = __float_as_uint(base[0]);
                a[mt][1] = __float_as_uint(base[8 * SIM_STRIDE]);
                a[mt][2] = __float_as_uint(base[4]);
                a[mt][3] = __float_as_uint(base[8 * SIM_STRIDE + 4]);
            }
            #pragma unroll
            for (int nt = 0; nt < 8; nt++) {
                const float* base = Bs + (wn*64 + nt*8 + lg) * SIM_STRIDE + c0;
                b[nt][0] = __float_as_uint(base[0]);
                b[nt][1] = __float_as_uint(base[4]);
            }
            #pragma unroll
            for (int mt = 0; mt < 4; mt++)
                #pragma unroll
                for (int nt = 0; nt < 8; nt++)
                    asm volatile(
                        "mma.sync.aligned.m16n8k8.row.col.f32.tf32.tf32.f32 "
                        "{%0,%1,%2,%3}, {%4,%5,%6,%7}, {%8,%9}, {%0,%1,%2,%3};"
                        : "+f"(acc[mt][nt][0]), "+f"(acc[mt][nt][1]),
                          "+f"(acc[mt][nt][2]), "+f"(acc[mt][nt][3])
                        : "r"(a[mt][0]), "r"(a[mt][1]), "r"(a[mt][2]), "r"(a[mt][3]),
                          "r"(b[nt][0]), "r"(b[nt][1]));
        }
        __syncthreads();
        buf ^= 1;
    }

    // epilogue
    #pragma unroll
    for (int mt = 0; mt < 4; mt++) {
        int row0 = wm*64 + mt*16 + lg;
        float ra0 = 1.f, ra1 = 1.f;
        if (donorm) { ra0 = rA[row0]; ra1 = rA[row0 + 8]; }
        #pragma unroll
        for (int nt = 0; nt < 8; nt++) {
            int col0 = wn*64 + nt*8 + 2*lc;
            float rb0 = 1.f, rb1 = 1.f;
            if (donorm) { rb0 = rB[col0]; rb1 = rB[col0 + 1]; }
            float2 v0 = make_float2(acc[mt][nt][0] * ra0 * rb0,
                                    acc[mt][nt][1] * ra0 * rb1);
            float2 v1 = make_float2(acc[mt][nt][2] * ra1 * rb0,
                                    acc[mt][nt][3] * ra1 * rb1);
            *(float2*)(out + row0 * 128 + col0) = v0;
            *(float2*)(out + (row0 + 8) * 128 + col0) = v1;
        }
    }
}

// ---------------- 4) barrier-free warp DP ----------------
// 64 blocks (0..31 LCS, 32..63 FSD), 128 threads (warp0 computes).
#define DP_PAD 130
#define DP_SMEM_BYTES (2 * 128 * DP_PAD * 4)

__global__ void dp_kernel(const int* __restrict__ pos,
                          const int* __restrict__ neg) {
    extern __shared__ float sh[];
    float* Ms = sh;
    float* Gs = sh + 128 * DP_PAD;

    int blk = blockIdx.x;
    int t = threadIdx.x;
    bool is_fsd = blk >= 32;
    int p = is_fsd ? blk - 32 : blk;

    if (!is_fsd) {
        int ia, ib;
        if (p < 16) { ia = pos[2*p]; ib = pos[2*p+1]; }
        else        { ia = neg[2*(p-16)]; ib = neg[2*(p-16)+1]; }
        const float* h0 = g_S + (size_t)(2*p) * 16384;
        const float* h1 = g_S + (size_t)(2*p + 1) * 16384;
        const float* rA = g_rn + ia * LL;
        const float* rB = g_rn + ib * LL;
        for (int q = t; q < 16384; q += 128) {
            int i = q >> 7, j = q & 127;
            float v = (h0[q] + h1[q]) * rA[i] * rB[j];
            Ms[i * DP_PAD + j] = fmaxf(0.f, v - 0.8f) * 5.0f;
        }
    } else {
        const float* m = g_S + (size_t)(64 + p) * 16384;
        const float* g = g_S + (size_t)(96 + p) * 16384;
        for (int q = t; q < 16384; q += 128) {
            int i = q >> 7, j = q & 127;
            Ms[i * DP_PAD + j] = m[q];
            Gs[i * DP_PAD + j] = g[q];
        }
    }
    __syncthreads();

    if (t >= 32) return;
    int lane = t;

    float cur[4]  = {0.f, 0.f, 0.f, 0.f};
    float prev[4] = {0.f, 0.f, 0.f, 0.f};
    float mv[4], gv[4] = {0.f, 0.f, 0.f, 0.f};

    // load matrix values for step s (j = s - i)
    #pragma unroll
    for (int r = 0; r < 4; r++) {
        int i = lane * 4 + r;
        int j = 0 - i;
        bool vld = (j >= 0 && j < 128);
        int idx = i * DP_PAD + (vld ? j : 0);
        mv[r] = vld ? Ms[idx] : 0.f;
        if (is_fsd) gv[r] = vld ? Gs[idx] : 0.f;
    }

    for (int s = 0; s < 255; s++) {
        // prefetch step s+1
        float nmv[4], ngv[4];
        #pragma unroll
        for (int r = 0; r < 4; r++) {
            int i = lane * 4 + r;
            int j = s + 1 - i;
            bool vld = (j >= 0 && j < 128);
            int idx = i * DP_PAD + (vld ? j : 0);
            nmv[r] = vld ? Ms[idx] : 0.f;
            ngv[r] = (is_fsd && vld) ? Gs[idx] : 0.f;
        }

        float upsh = __shfl_up_sync(0xffffffffu, cur[3], 1);
        float dgsh = __shfl_up_sync(0xffffffffu, prev[3], 1);
        if (lane == 0) { upsh = 0.f; dgsh = 0.f; }

        #pragma unroll
        for (int r = 3; r >= 0; r--) {
            int i = lane * 4 + r;
            int j = s - i;
            float up   = (r == 0) ? upsh : cur[r-1];
            float dg   = (r == 0) ? dgsh : prev[r-1];
            float left = cur[r];
            if (j == 0) { left = 0.f; dg = 0.f; }
            float nv;
            if (is_fsd) {
                float a0 = dg;
                float a1 = gv[r] + up;
                float a2 = gv[r] + left;
                float mx = fmaxf(a0, fmaxf(a1, a2));
                float se = __expf((a0 - mx) * 10.0f)
                         + __expf((a1 - mx) * 10.0f)
                         + __expf((a2 - mx) * 10.0f);
                nv = mv[r] + mx + 0.1f * __logf(se);
            } else {
                float sv = mv[r];
                nv = (sv > 0.5f) ? (dg + sv) : fmaxf(up, left);
            }
            prev[r] = cur[r];
            if (j >= 0 && j < 128) cur[r] = nv;
        }
        #pragma unroll
        for (int r = 0; r < 4; r++) { mv[r] = nmv[r]; gv[r] = ngv[r]; }
    }
    if (lane == 31) g_dp[blk] = cur[3];
}

// ---------------- 5) final combine ----------------
__global__ void final_kernel(const float* __restrict__ xi,
                             const float* __restrict__ xc,
                             const float* __restrict__ xb,
                             const float* __restrict__ vid,
                             float* __restrict__ out) {
    int b = threadIdx.x;
    const float EPS = 1e-45f;

    float s = 0.f;
    for (int c = 0; c < NC; c++) s += vid[b * NC + c];
    float li = 0.f, lcc = 0.f;
    for (int c = 0; c < NC; c++) {
        float v = vid[b * NC + c];
        if (v != 0.f) {
            li  += logf(xi[b * 21 + c] + EPS) * v;
            lcc += logf(xc[b * 21 + c] + EPS) * v;
        }
    }
    lcc += logf(xc[b * 21 + 20] + EPS);
    float lb = logf(xb[b * 21 + 20] + EPS);
    float cls_b = -(li / s) - (lcc / (s + 1.0f)) - lb;

    float guide = g_bstats[b*5+0];
    float sp    = g_bstats[b*5+1];
    float ni    = g_bstats[b*5+2];
    float nc2   = g_bstats[b*5+3];
    float nb    = g_bstats[b*5+4];
    float f1 = fmaxf(50.0f - ni + nc2, 0.f);
    float f2 = fmaxf(50.0f - nc2 + nb, 0.f);
    float fsum = f1 + f2 + nb;
    float feat_b = fsum * fsum;

    float lcs_v = g_dp[b];
    float fsd_v = g_dp[32 + b];
    float sign = (b < 16) ? -1.0f : 1.0f;

    float tot = cls_b * (1.0f / 32.0f)
              + guide * (1.0f / 32.0f)
              + 5e-5f * feat_b * (1.0f / 32.0f)
              + 2e-4f * sp * (1.0f / 64.0f)
              + 0.1f * sign * lcs_v * (1.0f / 16.0f)
              + 0.1f * sign * fsd_v * (1.0f / 16.0f);

    tot = warpSum(tot);
    if (b == 0) out[0] = tot;
}

// ---------------- launch ----------------
extern "C" void kernel_launch(void* const* d_in, const int* in_sizes, int n_in,
                              void* d_out, int out_size) {
    const float* xi   = (const float*)d_in[0];
    const float* xc   = (const float*)d_in[1];
    const float* xb   = (const float*)d_in[2];
    const float* vid  = (const float*)d_in[3];
    const float* att  = (const float*)d_in[4];
    const float* fi   = (const float*)d_in[5];
    const float* fc   = (const float*)d_in[6];
    const float* fbk  = (const float*)d_in[7];
    const float* cas  = (const float*)d_in[8];
    const float* lcs  = (const float*)d_in[9];
    const float* fa   = (const float*)d_in[10];
    const float* fb   = (const float*)d_in[11];
    const int*   pos  = (const int*)d_in[12];
    const int*   neg  = (const int*)d_in[13];
    float* out = (float*)d_out;

    cudaFuncSetAttribute(sim_kernel, cudaFuncAttributeMaxDynamicSharedMemorySize, SIM_SMEM);
    cudaFuncSetAttribute(dp_kernel, cudaFuncAttributeMaxDynamicSharedMemorySize, DP_SMEM_BYTES);

    norm_kernel<<<4096, 128>>>(lcs, fa, fb);
    bstats_kernel<<<BSZ, 256>>>(att, cas, fi, fc, fbk);
    sim_kernel<<<128, 128, SIM_SMEM>>>(lcs, fa, fb, pos, neg);
    dp_kernel<<<64, 128, DP_SMEM_BYTES>>>(pos, neg);
    final_kernel<<<1, 32>>>(xi, xc, xb, vid, out);
}

// round 3
// speedup vs baseline: 1.6701x; 1.0583x over previous
#include <cuda_runtime.h>
#include <math.h>

#define LL 128
#define DD 2048
#define BSZ 32
#define TT 2048
#define NC 20
#define SLOT 32768

// ---------------- device scratch ----------------
// diag-major sim matrices: slot z, element (i,j) at s*128+i, s=i+j
// z 0..63: LCS raw dot halves (pair p half h -> z=2p+h)
// z 64..95: FSD-M raw, z 96..127: FSD-G raw
__device__ float g_S[128 * SLOT];
__device__ float g_rn[5 * 4096];     // 0 lcs full, 1 act-m, 2 act-g, 3 bak-m, 4 bak-g
__device__ float g_bstats[BSZ * 5];
__device__ float g_dp[64];

__device__ __forceinline__ float warpSum(float v) {
    #pragma unroll
    for (int o = 16; o > 0; o >>= 1) v += __shfl_down_sync(0xffffffffu, v, o);
    return v;
}

// ---------------- 1) fused norms + batch stats ----------------
// grid 4128: blocks 0..4095 row norms, 4096..4127 per-batch stats. 128 thr.
__global__ void prep_kernel(const float* __restrict__ lcs,
                            const float* __restrict__ fa,
                            const float* __restrict__ fb,
                            const float* __restrict__ att,
                            const float* __restrict__ cas,
                            const float* __restrict__ fi,
                            const float* __restrict__ fc,
                            const float* __restrict__ fbk) {
    __shared__ float red[5][4];
    int t = threadIdx.x;
    int w = t >> 5, lane = t & 31;

    if (blockIdx.x < 4096) {
        int r = blockIdx.x;
        const float4* lrow = (const float4*)(lcs + (size_t)r * DD);
        const float4* arow = (const float4*)(fa  + (size_t)r * DD);
        const float4* brow = (const float4*)(fb  + (size_t)r * DD);
        float s_l = 0.f, s_am = 0.f, s_ag = 0.f, s_bm = 0.f, s_bg = 0.f;
        for (int q = t; q < 512; q += 128) {
            float4 v = lrow[q];
            s_l += v.x*v.x + v.y*v.y + v.z*v.z + v.w*v.w;
            float4 a = arow[q];
            float sa = a.x*a.x + a.y*a.y + a.z*a.z + a.w*a.w;
            float4 b = brow[q];
            float sb = b.x*b.x + b.y*b.y + b.z*b.z + b.w*b.w;
            if (q < 256) { s_am += sa; s_bm += sb; }
            else         { s_ag += sa; s_bg += sb; }
        }
        float vals[5] = {s_l, s_am, s_ag, s_bm, s_bg};
        #pragma unroll
        for (int k = 0; k < 5; k++) {
            float s = warpSum(vals[k]);
            if (lane == 0) red[k][w] = s;
        }
        __syncthreads();
        if (t == 0) {
            #pragma unroll
            for (int k = 0; k < 5; k++) {
                float s = red[k][0] + red[k][1] + red[k][2] + red[k][3];
                g_rn[k * 4096 + r] = 1.0f / sqrtf(s);
            }
        }
    } else {
        int b = blockIdx.x - 4096;
        float guide = 0.f, sp = 0.f, ni = 0.f, nc = 0.f, nb = 0.f;
        for (int q = t; q < TT; q += 128) {
            float c  = cas[((size_t)b * TT + q) * 21 + 20];
            float a0 = att[((size_t)b * TT + q) * 3 + 0];
            float a1 = att[((size_t)b * TT + q) * 3 + 1];
            guide += fabsf(1.0f - c - a0);
            sp += a0 + a1;
        }
        for (int q = t; q < DD; q += 128) {
            float x;
            x = fi [b * DD + q]; ni += x * x;
            x = fc [b * DD + q]; nc += x * x;
            x = fbk[b * DD + q]; nb += x * x;
        }
        float vals[5] = {guide, sp, ni, nc, nb};
        #pragma unroll
        for (int k = 0; k < 5; k++) {
            float s = warpSum(vals[k]);
            if (lane == 0) red[k][w] = s;
        }
        __syncthreads();
        if (t == 0) {
            float s0=0,s1=0,s2=0,s3=0,s4=0;
            #pragma unroll
            for (int w2 = 0; w2 < 4; w2++) {
                s0 += red[0][w2]; s1 += red[1][w2]; s2 += red[2][w2];
                s3 += red[3][w2]; s4 += red[4][w2];
            }
            g_bstats[b*5+0] = s0;
            g_bstats[b*5+1] = s1;
            g_bstats[b*5+2] = sqrtf(s2);
            g_bstats[b*5+3] = sqrtf(s3);
            g_bstats[b*5+4] = sqrtf(s4);
        }
    }
}

// ---------------- 2) tf32 mma similarity GEMM (raw dots, diag-major out) ----
#define SIM_STRIDE 36
#define SIM_TILE   (128 * SIM_STRIDE)
#define SIM_SMEM   (4 * SIM_TILE * 4)

__device__ __forceinline__ void cp16(float* smem_dst, const float* gsrc) {
    unsigned s = (unsigned)__cvta_generic_to_shared(smem_dst);
    asm volatile("cp.async.cg.shared.global [%0], [%1], 16;\n" :: "r"(s), "l"(gsrc));
}

__global__ void __launch_bounds__(128, 1)
sim_kernel(const float* __restrict__ lcs,
           const float* __restrict__ fa,
           const float* __restrict__ fb,
           const int* __restrict__ pos,
           const int* __restrict__ neg) {
    extern __shared__ float sh[];
    float* Abuf = sh;
    float* Bbuf = sh + 2 * SIM_TILE;

    int z = blockIdx.x;
    int t = threadIdx.x;
    int w = t >> 5, lane = t & 31;
    int wm = w >> 1, wn = w & 1;
    int lg = lane >> 2, lc = lane & 3;

    int p, koff;
    if (z < 64) { p = z >> 1; koff = (z & 1) * 1024; }
    else if (z < 96) { p = z - 64; koff = 0; }
    else { p = z - 96; koff = 1024; }

    int ia, ib;
    if (p < 16) { ia = pos[2*p]; ib = pos[2*p+1]; }
    else        { ia = neg[2*(p-16)]; ib = neg[2*(p-16)+1]; }

    const float *abase, *bbase;
    if (z < 64) {
        abase = lcs + (size_t)ia * LL * DD + koff;
        bbase = lcs + (size_t)ib * LL * DD + koff;
    } else {
        abase = fa + (size_t)ia * LL * DD + koff;
        bbase = ((p < 16) ? fa : fb) + (size_t)ib * LL * DD + koff;
    }
    float* out = g_S + (size_t)z * SLOT;

    float acc[4][8][4];
    #pragma unroll
    for (int mt = 0; mt < 4; mt++)
        #pragma unroll
        for (int nt = 0; nt < 8; nt++)
            #pragma unroll
            for (int j = 0; j < 4; j++) acc[mt][nt][j] = 0.f;

    #pragma unroll
    for (int u = 0; u < 8; u++) {
        int fq = u * 128 + t;
        int r = fq >> 3, cq = fq & 7;
        cp16(Abuf + r * SIM_STRIDE + cq * 4, abase + (size_t)r * DD + cq * 4);
        cp16(Bbuf + r * SIM_STRIDE + cq * 4, bbase + (size_t)r * DD + cq * 4);
    }
    asm volatile("cp.async.commit_group;\n");

    int buf = 0;
    for (int it = 0; it < 32; it++) {
        if (it + 1 < 32) {
            float* Ad = Abuf + (buf ^ 1) * SIM_TILE;
            float* Bd = Bbuf + (buf ^ 1) * SIM_TILE;
            int kt = (it + 1) * 32;
            #pragma unroll
            for (int u = 0; u < 8; u++) {
                int fq = u * 128 + t;
                int r = fq >> 3, cq = fq & 7;
                cp16(Ad + r * SIM_STRIDE + cq * 4, abase + (size_t)r * DD + kt + cq * 4);
                cp16(Bd + r * SIM_STRIDE + cq * 4, bbase + (size_t)r * DD + kt + cq * 4);
            }
        }
        asm volatile("cp.async.commit_group;\n");
        asm volatile("cp.async.wait_group 1;\n");
        __syncthreads();

        const float* As = Abuf + buf * SIM_TILE;
        const float* Bs = Bbuf + buf * SIM_TILE;
        #pragma unroll
        for (int ks = 0; ks < 4; ks++) {
            unsigned a[4][4], b[8][2];
            int c0 = ks * 8 + lc;
            #pragma unroll
            for (int mt = 0; mt < 4; mt++) {
                const float* base = As + (wm*64 + mt*16 + lg) * SIM_STRIDE + c0;
                a[mt][0] = __float_as_uint(base[0]);
                a[mt][1] = __float_as_uint(base[8 * SIM_STRIDE]);
                a[mt][2] = __float_as_uint(base[4]);
                a[mt][3] = __float_as_uint(base[8 * SIM_STRIDE + 4]);
            }
            #pragma unroll
            for (int nt = 0; nt < 8; nt++) {
                const float* base = Bs + (wn*64 + nt*8 + lg) * SIM_STRIDE + c0;
                b[nt][0] = __float_as_uint(base[0]);
                b[nt][1] = __float_as_uint(base[4]);
            }
            #pragma unroll
            for (int mt = 0; mt < 4; mt++)
                #pragma unroll
                for (int nt = 0; nt < 8; nt++)
                    asm volatile(
                        "mma.sync.aligned.m16n8k8.row.col.f32.tf32.tf32.f32 "
                        "{%0,%1,%2,%3}, {%4,%5,%6,%7}, {%8,%9}, {%0,%1,%2,%3};"
                        : "+f"(acc[mt][nt][0]), "+f"(acc[mt][nt][1]),
                          "+f"(acc[mt][nt][2]), "+f"(acc[mt][nt][3])
                        : "r"(a[mt][0]), "r"(a[mt][1]), "r"(a[mt][2]), "r"(a[mt][3]),
                          "r"(b[nt][0]), "r"(b[nt][1]));
        }
        __syncthreads();
        buf ^= 1;
    }

    // diag-major epilogue: (i,j) -> (i+j)*128 + i
    #pragma unroll
    for (int mt = 0; mt < 4; mt++) {
        int row0 = wm*64 + mt*16 + lg;
        #pragma unroll
        for (int nt = 0; nt < 8; nt++) {
            int col0 = wn*64 + nt*8 + 2*lc;
            out[(row0 + col0) * 128 + row0]           = acc[mt][nt][0];
            out[(row0 + col0 + 1) * 128 + row0]       = acc[mt][nt][1];
            out[(row0 + 8 + col0) * 128 + row0 + 8]   = acc[mt][nt][2];
            out[(row0 + 8 + col0 + 1) * 128 + row0+8] = acc[mt][nt][3];
        }
    }
}

// ---------------- 3) streaming warp DP ----------------
// 64 blocks x 32 threads. Lane l owns rows 4l..4l+3. Diag-major LDG.128 stream.
__global__ void __launch_bounds__(32, 1)
dp_kernel(const int* __restrict__ pos, const int* __restrict__ neg) {
    __shared__ float sB[256];
    int blk = blockIdx.x;
    int lane = threadIdx.x;
    bool is_fsd = blk >= 32;
    int p = is_fsd ? blk - 32 : blk;
    int ia, ib;
    if (p < 16) { ia = pos[2*p]; ib = pos[2*p+1]; }
    else        { ia = neg[2*(p-16)]; ib = neg[2*(p-16)+1]; }

    const float *m0, *m1;
    float rA0[4], rA1[4];
    if (!is_fsd) {
        m0 = g_S + (size_t)(2*p) * SLOT;
        m1 = g_S + (size_t)(2*p + 1) * SLOT;
        const float* rnA = g_rn + ia * LL;
        const float* rnB = g_rn + ib * LL;
        #pragma unroll
        for (int r = 0; r < 4; r++) { rA0[r] = rnA[lane*4 + r]; rA1[r] = 0.f; }
        for (int q = lane; q < 128; q += 32) { sB[q] = rnB[q]; sB[128+q] = 0.f; }
    } else {
        m0 = g_S + (size_t)(64 + p) * SLOT;
        m1 = g_S + (size_t)(96 + p) * SLOT;
        const float* rnMA = g_rn + 1*4096 + ia * LL;
        const float* rnGA = g_rn + 2*4096 + ia * LL;
        const float* rnMB = g_rn + ((p < 16) ? 1 : 3)*4096 + ib * LL;
        const float* rnGB = g_rn + ((p < 16) ? 2 : 4)*4096 + ib * LL;
        #pragma unroll
        for (int r = 0; r < 4; r++) { rA0[r] = rnMA[lane*4+r]; rA1[r] = rnGA[lane*4+r]; }
        for (int q = lane; q < 128; q += 32) { sB[q] = rnMB[q]; sB[128+q] = rnGB[q]; }
    }
    __syncwarp();

    float cur[4]  = {0.f, 0.f, 0.f, 0.f};
    float prev[4] = {0.f, 0.f, 0.f, 0.f};
    float4 mq[4], gq[4];
    #pragma unroll
    for (int u = 0; u < 4; u++) {
        mq[u] = *(const float4*)(m0 + u*128 + lane*4);
        gq[u] = *(const float4*)(m1 + u*128 + lane*4);
    }

    const float S2L = 14.42695040888963f;    // 10 * log2(e)
    const float KLN = 0.06931471805599453f;  // 0.1 * ln(2)

    for (int s4 = 0; s4 < 256; s4 += 4) {
        #pragma unroll
        for (int u = 0; u < 4; u++) {
            int s = s4 + u;
            float rm[4] = {mq[u].x, mq[u].y, mq[u].z, mq[u].w};
            float rg[4] = {gq[u].x, gq[u].y, gq[u].z, gq[u].w};
            int spf = s + 4; if (spf > 255) spf = 255;
            mq[u] = *(const float4*)(m0 + spf*128 + lane*4);
            gq[u] = *(const float4*)(m1 + spf*128 + lane*4);

            float upsh = __shfl_up_sync(0xffffffffu, cur[3], 1);
            float dgsh = __shfl_up_sync(0xffffffffu, prev[3], 1);
            if (lane == 0) { upsh = 0.f; dgsh = 0.f; }

            float nv[4];
            #pragma unroll
            for (int r = 0; r < 4; r++) {
                int i = lane*4 + r;
                int jc = (s - i) & 127;
                float up   = r ? cur[r-1]  : upsh;
                float dg   = r ? prev[r-1] : dgsh;
                float left = cur[r];
                if (s == i) { left = 0.f; dg = 0.f; }
                if (!is_fsd) {
                    float v = (rm[r] + rg[r]) * rA0[r] * sB[jc];
                    float sv = fmaxf(0.f, (v - 0.8f) * 5.0f);
                    nv[r] = (sv > 0.5f) ? (dg + sv) : fmaxf(up, left);
                } else {
                    float mv = rm[r] * rA0[r] * sB[jc];
                    float gv = rg[r] * rA1[r] * sB[128 + jc];
                    float a0 = dg;
                    float a1 = gv + up;
                    float a2 = gv + left;
                    float m12 = fmaxf(a1, a2), n12 = fminf(a1, a2);
                    float mx  = fmaxf(a0, m12), mn = fminf(a0, m12);
                    float tt = -mx * S2L;
                    float x1 = fmaf(mn,  S2L, tt);
                    float x2 = fmaf(n12, S2L, tt);
                    float e1, e2, lg;
                    asm("ex2.approx.ftz.f32 %0, %1;" : "=f"(e1) : "f"(x1));
                    asm("ex2.approx.ftz.f32 %0, %1;" : "=f"(e2) : "f"(x2));
                    float se = 1.0f + e1 + e2;
                    asm("lg2.approx.ftz.f32 %0, %1;" : "=f"(lg) : "f"(se));
                    nv[r] = fmaf(lg, KLN, mv + mx);
                }
            }
            #pragma unroll
            for (int r = 0; r < 4; r++) {
                int i = lane*4 + r;
                prev[r] = cur[r];
                if ((unsigned)(s - i) < 128u) cur[r] = nv[r];
            }
        }
    }
    if (lane == 31) g_dp[blk] = cur[3];
}

// ---------------- 4) final combine ----------------
__global__ void final_kernel(const float* __restrict__ xi,
                             const float* __restrict__ xc,
                             const float* __restrict__ xb,
                             const float* __restrict__ vid,
                             float* __restrict__ out) {
    int b = threadIdx.x;
    const float EPS = 1e-45f;

    float s = 0.f;
    for (int c = 0; c < NC; c++) s += vid[b * NC + c];
    float li = 0.f, lcc = 0.f;
    for (int c = 0; c < NC; c++) {
        float v = vid[b * NC + c];
        if (v != 0.f) {
            li  += logf(xi[b * 21 + c] + EPS) * v;
            lcc += logf(xc[b * 21 + c] + EPS) * v;
        }
    }
    lcc += logf(xc[b * 21 + 20] + EPS);
    float lb = logf(xb[b * 21 + 20] + EPS);
    float cls_b = -(li / s) - (lcc / (s + 1.0f)) - lb;

    float guide = g_bstats[b*5+0];
    float sp    = g_bstats[b*5+1];
    float ni    = g_bstats[b*5+2];
    float nc2   = g_bstats[b*5+3];
    float nb    = g_bstats[b*5+4];
    float f1 = fmaxf(50.0f - ni + nc2, 0.f);
    float f2 = fmaxf(50.0f - nc2 + nb, 0.f);
    float fsum = f1 + f2 + nb;
    float feat_b = fsum * fsum;

    float lcs_v = g_dp[b];
    float fsd_v = g_dp[32 + b];
    float sign = (b < 16) ? -1.0f : 1.0f;

    float tot = cls_b * (1.0f / 32.0f)
              + guide * (1.0f / 32.0f)
              + 5e-5f * feat_b * (1.0f / 32.0f)
              + 2e-4f * sp * (1.0f / 64.0f)
              + 0.1f * sign * lcs_v * (1.0f / 16.0f)
              + 0.1f * sign * fsd_v * (1.0f / 16.0f);

    tot = warpSum(tot);
    if (b == 0) out[0] = tot;
}

// ---------------- launch ----------------
extern "C" void kernel_launch(void* const* d_in, const int* in_sizes, int n_in,
                              void* d_out, int out_size) {
    const float* xi   = (const float*)d_in[0];
    const float* xc   = (const float*)d_in[1];
    const float* xb   = (const float*)d_in[2];
    const float* vid  = (const float*)d_in[3];
    const float* att  = (const float*)d_in[4];
    const float* fi   = (const float*)d_in[5];
    const float* fc   = (const float*)d_in[6];
    const float* fbk  = (const float*)d_in[7];
    const float* cas  = (const float*)d_in[8];
    const float* lcs  = (const float*)d_in[9];
    const float* fa   = (const float*)d_in[10];
    const float* fb   = (const float*)d_in[11];
    const int*   pos  = (const int*)d_in[12];
    const int*   neg  = (const int*)d_in[13];
    float* out = (float*)d_out;

    cudaFuncSetAttribute(sim_kernel, cudaFuncAttributeMaxDynamicSharedMemorySize, SIM_SMEM);

    sim_kernel<<<128, 128, SIM_SMEM>>>(lcs, fa, fb, pos, neg);
    prep_kernel<<<4128, 128>>>(lcs, fa, fb, att, cas, fi, fc, fbk);
    dp_kernel<<<64, 32>>>(pos, neg);
    final_kernel<<<1, 32>>>(xi, xc, xb, vid, out);
}

// round 6
// speedup vs baseline: 2.4719x; 1.4801x over previous
#include <cuda_runtime.h>
#include <math.h>

#define LL 128
#define DD 2048
#define BSZ 32
#define TT 2048
#define NC 20
#define SLOT 16384

// ---------------- device scratch ----------------
// row-major sim matrices, all normalized:
// z 0..63: LCS normalized dot halves (pair p half h -> z=2p+h)
// z 64..95: FSD-M, z 96..127: FSD-G
__device__ float g_S[128 * SLOT];
__device__ float g_rn[5 * 4096];     // 0 lcs, 1 act-m, 2 act-g, 3 bak-m, 4 bak-g
__device__ float g_bstats[BSZ * 5];
__device__ float g_dp[64];

__device__ __forceinline__ float warpSum(float v) {
    #pragma unroll
    for (int o = 16; o > 0; o >>= 1) v += __shfl_down_sync(0xffffffffu, v, o);
    return v;
}

// ---------------- 1) fused norms + batch stats ----------------
__global__ void prep_kernel(const float* __restrict__ lcs,
                            const float* __restrict__ fa,
                            const float* __restrict__ fb,
                            const float* __restrict__ att,
                            const float* __restrict__ cas,
                            const float* __restrict__ fi,
                            const float* __restrict__ fc,
                            const float* __restrict__ fbk) {
    __shared__ float red[5][4];
    int t = threadIdx.x;
    int w = t >> 5, lane = t & 31;

    if (blockIdx.x < 4096) {
        int r = blockIdx.x;
        const float4* lrow = (const float4*)(lcs + (size_t)r * DD);
        const float4* arow = (const float4*)(fa  + (size_t)r * DD);
        const float4* brow = (const float4*)(fb  + (size_t)r * DD);
        float s_l = 0.f, s_am = 0.f, s_ag = 0.f, s_bm = 0.f, s_bg = 0.f;
        for (int q = t; q < 512; q += 128) {
            float4 v = lrow[q];
            s_l += v.x*v.x + v.y*v.y + v.z*v.z + v.w*v.w;
            float4 a = arow[q];
            float sa = a.x*a.x + a.y*a.y + a.z*a.z + a.w*a.w;
            float4 b = brow[q];
            float sb = b.x*b.x + b.y*b.y + b.z*b.z + b.w*b.w;
            if (q < 256) { s_am += sa; s_bm += sb; }
            else         { s_ag += sa; s_bg += sb; }
        }
        float vals[5] = {s_l, s_am, s_ag, s_bm, s_bg};
        #pragma unroll
        for (int k = 0; k < 5; k++) {
            float s = warpSum(vals[k]);
            if (lane == 0) red[k][w] = s;
        }
        __syncthreads();
        if (t == 0) {
            #pragma unroll
            for (int k = 0; k < 5; k++) {
                float s = red[k][0] + red[k][1] + red[k][2] + red[k][3];
                g_rn[k * 4096 + r] = 1.0f / sqrtf(s);
            }
        }
    } else {
        int b = blockIdx.x - 4096;
        float guide = 0.f, sp = 0.f, ni = 0.f, nc = 0.f, nb = 0.f;
        for (int q = t; q < TT; q += 128) {
            float c  = cas[((size_t)b * TT + q) * 21 + 20];
            float a0 = att[((size_t)b * TT + q) * 3 + 0];
            float a1 = att[((size_t)b * TT + q) * 3 + 1];
            guide += fabsf(1.0f - c - a0);
            sp += a0 + a1;
        }
        for (int q = t; q < DD; q += 128) {
            float x;
            x = fi [b * DD + q]; ni += x * x;
            x = fc [b * DD + q]; nc += x * x;
            x = fbk[b * DD + q]; nb += x * x;
        }
        float vals[5] = {guide, sp, ni, nc, nb};
        #pragma unroll
        for (int k = 0; k < 5; k++) {
            float s = warpSum(vals[k]);
            if (lane == 0) red[k][w] = s;
        }
        __syncthreads();
        if (t == 0) {
            float s0=0,s1=0,s2=0,s3=0,s4=0;
            #pragma unroll
            for (int w2 = 0; w2 < 4; w2++) {
                s0 += red[0][w2]; s1 += red[1][w2]; s2 += red[2][w2];
                s3 += red[3][w2]; s4 += red[4][w2];
            }
            g_bstats[b*5+0] = s0;
            g_bstats[b*5+1] = s1;
            g_bstats[b*5+2] = sqrtf(s2);
            g_bstats[b*5+3] = sqrtf(s3);
            g_bstats[b*5+4] = sqrtf(s4);
        }
    }
}

// ---------------- 2) tf32 mma similarity GEMM (normalized, row-major) ------
#define SIM_STRIDE 36
#define SIM_TILE   (128 * SIM_STRIDE)
#define SIM_SMEM   (4 * SIM_TILE * 4)

__device__ __forceinline__ void cp16(float* smem_dst, const float* gsrc) {
    unsigned s = (unsigned)__cvta_generic_to_shared(smem_dst);
    asm volatile("cp.async.cg.shared.global [%0], [%1], 16;\n" :: "r"(s), "l"(gsrc));
}

__global__ void __launch_bounds__(128, 1)
sim_kernel(const float* __restrict__ lcs,
           const float* __restrict__ fa,
           const float* __restrict__ fb,
           const int* __restrict__ pos,
           const int* __restrict__ neg) {
    extern __shared__ float sh[];
    float* Abuf = sh;
    float* Bbuf = sh + 2 * SIM_TILE;

    int z = blockIdx.x;
    int t = threadIdx.x;
    int w = t >> 5, lane = t & 31;
    int wm = w >> 1, wn = w & 1;
    int lg = lane >> 2, lc = lane & 3;

    int p, koff;
    if (z < 64) { p = z >> 1; koff = (z & 1) * 1024; }
    else if (z < 96) { p = z - 64; koff = 0; }
    else { p = z - 96; koff = 1024; }

    int ia, ib;
    if (p < 16) { ia = pos[2*p]; ib = pos[2*p+1]; }
    else        { ia = neg[2*(p-16)]; ib = neg[2*(p-16)+1]; }

    const float *abase, *bbase, *rA, *rB;
    if (z < 64) {
        abase = lcs + (size_t)ia * LL * DD + koff;
        bbase = lcs + (size_t)ib * LL * DD + koff;
        rA = g_rn + ia * LL;
        rB = g_rn + ib * LL;
    } else {
        int half = (z < 96) ? 0 : 1;
        abase = fa + (size_t)ia * LL * DD + koff;
        bbase = ((p < 16) ? fa : fb) + (size_t)ib * LL * DD + koff;
        rA = g_rn + (1 + half) * 4096 + ia * LL;
        rB = g_rn + (((p < 16) ? 1 : 3) + half) * 4096 + ib * LL;
    }
    float* out = g_S + (size_t)z * SLOT;

    float acc[4][8][4];
    #pragma unroll
    for (int mt = 0; mt < 4; mt++)
        #pragma unroll
        for (int nt = 0; nt < 8; nt++)
            #pragma unroll
            for (int j = 0; j < 4; j++) acc[mt][nt][j] = 0.f;

    #pragma unroll
    for (int u = 0; u < 8; u++) {
        int fq = u * 128 + t;
        int r = fq >> 3, cq = fq & 7;
        cp16(Abuf + r * SIM_STRIDE + cq * 4, abase + (size_t)r * DD + cq * 4);
        cp16(Bbuf + r * SIM_STRIDE + cq * 4, bbase + (size_t)r * DD + cq * 4);
    }
    asm volatile("cp.async.commit_group;\n");

    int buf = 0;
    for (int it = 0; it < 32; it++) {
        if (it + 1 < 32) {
            float* Ad = Abuf + (buf ^ 1) * SIM_TILE;
            float* Bd = Bbuf + (buf ^ 1) * SIM_TILE;
            int kt = (it + 1) * 32;
            #pragma unroll
            for (int u = 0; u < 8; u++) {
                int fq = u * 128 + t;
                int r = fq >> 3, cq = fq & 7;
                cp16(Ad + r * SIM_STRIDE + cq * 4, abase + (size_t)r * DD + kt + cq * 4);
                cp16(Bd + r * SIM_STRIDE + cq * 4, bbase + (size_t)r * DD + kt + cq * 4);
            }
        }
        asm volatile("cp.async.commit_group;\n");
        asm volatile("cp.async.wait_group 1;\n");
        __syncthreads();

        const float* As = Abuf + buf * SIM_TILE;
        const float* Bs = Bbuf + buf * SIM_TILE;
        #pragma unroll
        for (int ks = 0; ks < 4; ks++) {
            unsigned a[4][4], b[8][2];
            int c0 = ks * 8 + lc;
            #pragma unroll
            for (int mt = 0; mt < 4; mt++) {
                const float* base = As + (wm*64 + mt*16 + lg) * SIM_STRIDE + c0;
                a[mt][0] = __float_as_uint(base[0]);
                a[mt][1] = __float_as_uint(base[8 * SIM_STRIDE]);
                a[mt][2] = __float_as_uint(base[4]);
                a[mt][3] = __float_as_uint(base[8 * SIM_STRIDE + 4]);
            }
            #pragma unroll
            for (int nt = 0; nt < 8; nt++) {
                const float* base = Bs + (wn*64 + nt*8 + lg) * SIM_STRIDE + c0;
                b[nt][0] = __float_as_uint(base[0]);
                b[nt][1] = __float_as_uint(base[4]);
            }
            #pragma unroll
            for (int mt = 0; mt < 4; mt++)
                #pragma unroll
                for (int nt = 0; nt < 8; nt++)
                    asm volatile(
                        "mma.sync.aligned.m16n8k8.row.col.f32.tf32.tf32.f32 "
                        "{%0,%1,%2,%3}, {%4,%5,%6,%7}, {%8,%9}, {%0,%1,%2,%3};"
                        : "+f"(acc[mt][nt][0]), "+f"(acc[mt][nt][1]),
                          "+f"(acc[mt][nt][2]), "+f"(acc[mt][nt][3])
                        : "r"(a[mt][0]), "r"(a[mt][1]), "r"(a[mt][2]), "r"(a[mt][3]),
                          "r"(b[nt][0]), "r"(b[nt][1]));
        }
        __syncthreads();
        buf ^= 1;
    }

    // normalized row-major epilogue (coalesced float2 stores)
    #pragma unroll
    for (int mt = 0; mt < 4; mt++) {
        int row0 = wm*64 + mt*16 + lg;
        float ra0 = rA[row0], ra1 = rA[row0 + 8];
        #pragma unroll
        for (int nt = 0; nt < 8; nt++) {
            int col0 = wn*64 + nt*8 + 2*lc;
            float rb0 = rB[col0], rb1 = rB[col0 + 1];
            float2 v0 = make_float2(acc[mt][nt][0] * ra0 * rb0,
                                    acc[mt][nt][1] * ra0 * rb1);
            float2 v1 = make_float2(acc[mt][nt][2] * ra1 * rb0,
                                    acc[mt][nt][3] * ra1 * rb1);
            *(float2*)(out + row0 * 128 + col0) = v0;
            *(float2*)(out + (row0 + 8) * 128 + col0) = v1;
        }
    }
}

// ---------------- 3) barrier wavefront DP (row-per-thread, intrinsics) -----
#define DP_STRIDE 130
#define DP_SMEM_BYTES ((2 * 128 * DP_STRIDE + 3 * 132) * 4)

__global__ void __launch_bounds__(128, 1)
dp_kernel() {
    extern __shared__ float sh[];
    float* Ms = sh;
    float* Gs = sh + 128 * DP_STRIDE;
    float* Pr = sh + 2 * 128 * DP_STRIDE;   // 3 rings of 132

    int blk = blockIdx.x;
    int t = threadIdx.x;
    bool is_fsd = blk >= 32;
    int p = is_fsd ? blk - 32 : blk;

    if (!is_fsd) {
        const float* h0 = g_S + (size_t)(2*p) * SLOT;
        const float* h1 = g_S + (size_t)(2*p + 1) * SLOT;
        for (int q = t; q < 16384; q += 128) {
            int i = q >> 7, j = q & 127;
            float v = h0[q] + h1[q];
            Ms[i * DP_STRIDE + j] = fmaxf(0.f, (v - 0.8f) * 5.0f);
        }
    } else {
        const float* m = g_S + (size_t)(64 + p) * SLOT;
        const float* g = g_S + (size_t)(96 + p) * SLOT;
        for (int q = t; q < 16384; q += 128) {
            int i = q >> 7, j = q & 127;
            Ms[i * DP_STRIDE + j] = m[q];
            Gs[i * DP_STRIDE + j] = g[q];
        }
    }
    for (int q = t; q < 3 * 132; q += 128) Pr[q] = 0.f;
    __syncthreads();

    float* P1 = Pr;          // step s-1
    float* P2 = Pr + 132;    // step s-2
    float* P0 = Pr + 264;    // write

    const float S2L = 14.42695040888963f;    // 10 * log2(e)
    const float KLN = 0.06931471805599453f;  // 0.1 * ln(2)

    float cur = 0.f;
    int base = t * DP_STRIDE;

    for (int s = 0; s < 255; s++) {
        int j = s - t;
        bool act = ((unsigned)j < 128u);
        float up = P1[t];
        float dg = P2[t];
        float lf = cur;
        if (j == 0) { lf = 0.f; dg = 0.f; }
        if (act) {
            float nv;
            if (is_fsd) {
                float m = Ms[base + j];
                float g = Gs[base + j];
                float a0 = dg;
                float a1 = g + up;
                float a2 = g + lf;
                float m12 = fmaxf(a1, a2), n12 = fminf(a1, a2);
                float mx  = fmaxf(a0, m12), mn = fminf(a0, m12);
                float tt = -mx * S2L;
                float x1 = fmaf(mn,  S2L, tt);
                float x2 = fmaf(n12, S2L, tt);
                float e1, e2, lgv;
                asm("ex2.approx.ftz.f32 %0, %1;" : "=f"(e1) : "f"(x1));
                asm("ex2.approx.ftz.f32 %0, %1;" : "=f"(e2) : "f"(x2));
                float se = 1.0f + e1 + e2;
                asm("lg2.approx.ftz.f32 %0, %1;" : "=f"(lgv) : "f"(se));
                nv = fmaf(lgv, KLN, m + mx);
            } else {
                float m = Ms[base + j];
                nv = (m > 0.5f) ? (dg + m) : fmaxf(up, lf);
            }
            cur = nv;
            P0[t + 1] = nv;
        }
        __syncthreads();
        float* tmp = P2; P2 = P1; P1 = P0; P0 = tmp;
    }
    if (t == 127) g_dp[blk] = cur;
}

// ---------------- 4) final combine ----------------
__global__ void final_kernel(const float* __restrict__ xi,
                             const float* __restrict__ xc,
                             const float* __restrict__ xb,
                             const float* __restrict__ vid,
                             float* __restrict__ out) {
    int b = threadIdx.x;
    const float EPS = 1e-45f;

    float s = 0.f;
    for (int c = 0; c < NC; c++) s += vid[b * NC + c];
    float li = 0.f, lcc = 0.f;
    for (int c = 0; c < NC; c++) {
        float v = vid[b * NC + c];
        if (v != 0.f) {
            li  += __logf(xi[b * 21 + c] + EPS) * v;
            lcc += __logf(xc[b * 21 + c] + EPS) * v;
        }
    }
    lcc += __logf(xc[b * 21 + 20] + EPS);
    float lb = __logf(xb[b * 21 + 20] + EPS);
    float cls_b = -(li / s) - (lcc / (s + 1.0f)) - lb;

    float guide = g_bstats[b*5+0];
    float sp    = g_bstats[b*5+1];
    float ni    = g_bstats[b*5+2];
    float nc2   = g_bstats[b*5+3];
    float nb    = g_bstats[b*5+4];
    float f1 = fmaxf(50.0f - ni + nc2, 0.f);
    float f2 = fmaxf(50.0f - nc2 + nb, 0.f);
    float fsum = f1 + f2 + nb;
    float feat_b = fsum * fsum;

    float lcs_v = g_dp[b];
    float fsd_v = g_dp[32 + b];
    float sign = (b < 16) ? -1.0f : 1.0f;

    float tot = cls_b * (1.0f / 32.0f)
              + guide * (1.0f / 32.0f)
              + 5e-5f * feat_b * (1.0f / 32.0f)
              + 2e-4f * sp * (1.0f / 64.0f)
              + 0.1f * sign * lcs_v * (1.0f / 16.0f)
              + 0.1f * sign * fsd_v * (1.0f / 16.0f);

    tot = warpSum(tot);
    if (b == 0) out[0] = tot;
}

// ---------------- launch ----------------
extern "C" void kernel_launch(void* const* d_in, const int* in_sizes, int n_in,
                              void* d_out, int out_size) {
    const float* xi   = (const float*)d_in[0];
    const float* xc   = (const float*)d_in[1];
    const float* xb   = (const float*)d_in[2];
    const float* vid  = (const float*)d_in[3];
    const float* att  = (const float*)d_in[4];
    const float* fi   = (const float*)d_in[5];
    const float* fc   = (const float*)d_in[6];
    const float* fbk  = (const float*)d_in[7];
    const float* cas  = (const float*)d_in[8];
    const float* lcs  = (const float*)d_in[9];
    const float* fa   = (const float*)d_in[10];
    const float* fb   = (const float*)d_in[11];
    const int*   pos  = (const int*)d_in[12];
    const int*   neg  = (const int*)d_in[13];
    float* out = (float*)d_out;

    cudaFuncSetAttribute(sim_kernel, cudaFuncAttributeMaxDynamicSharedMemorySize, SIM_SMEM);
    cudaFuncSetAttribute(dp_kernel, cudaFuncAttributeMaxDynamicSharedMemorySize, DP_SMEM_BYTES);

    prep_kernel<<<4128, 128>>>(lcs, fa, fb, att, cas, fi, fc, fbk);
    sim_kernel<<<128, 128, SIM_SMEM>>>(lcs, fa, fb, pos, neg);
    dp_kernel<<<64, 128, DP_SMEM_BYTES>>>();
    final_kernel<<<1, 32>>>(xi, xc, xb, vid, out);
}

// round 7
// speedup vs baseline: 2.6004x; 1.0520x over previous
#include <cuda_runtime.h>
#include <math.h>

#define LL 128
#define DD 2048
#define BSZ 32
#define TT 2048
#define NC 20
#define SLOT 16384

// ---------------- device scratch ----------------
// raw partial dot matrices, row-major 128x128:
// z 0..127  : LCS pair p=z>>2, K-quarter q=z&3 (koff=q*512)
// z 128..191: FSD-M pair p=(z-128)>>1, K-half h (koff=h*512)
// z 192..255: FSD-G pair p=(z-192)>>1, K-half h (koff=1024+h*512)
__device__ float g_S[256 * SLOT];
__device__ float g_rn[5 * 4096];     // 0 lcs, 1 act-m, 2 act-g, 3 bak-m, 4 bak-g
__device__ float g_bstats[BSZ * 5];
__device__ float g_dp[64];
__device__ int   g_ctr;

__device__ __forceinline__ float warpSum(float v) {
    #pragma unroll
    for (int o = 16; o > 0; o >>= 1) v += __shfl_down_sync(0xffffffffu, v, o);
    return v;
}

// ---------------- 1) fused norms + batch stats ----------------
__global__ void prep_kernel(const float* __restrict__ lcs,
                            const float* __restrict__ fa,
                            const float* __restrict__ fb,
                            const float* __restrict__ att,
                            const float* __restrict__ cas,
                            const float* __restrict__ fi,
                            const float* __restrict__ fc,
                            const float* __restrict__ fbk) {
    __shared__ float red[5][4];
    int t = threadIdx.x;
    int w = t >> 5, lane = t & 31;

    if (blockIdx.x < 4096) {
        int r = blockIdx.x;
        const float4* lrow = (const float4*)(lcs + (size_t)r * DD);
        const float4* arow = (const float4*)(fa  + (size_t)r * DD);
        const float4* brow = (const float4*)(fb  + (size_t)r * DD);
        float s_l = 0.f, s_am = 0.f, s_ag = 0.f, s_bm = 0.f, s_bg = 0.f;
        for (int q = t; q < 512; q += 128) {
            float4 v = lrow[q];
            s_l += v.x*v.x + v.y*v.y + v.z*v.z + v.w*v.w;
            float4 a = arow[q];
            float sa = a.x*a.x + a.y*a.y + a.z*a.z + a.w*a.w;
            float4 b = brow[q];
            float sb = b.x*b.x + b.y*b.y + b.z*b.z + b.w*b.w;
            if (q < 256) { s_am += sa; s_bm += sb; }
            else         { s_ag += sa; s_bg += sb; }
        }
        float vals[5] = {s_l, s_am, s_ag, s_bm, s_bg};
        #pragma unroll
        for (int k = 0; k < 5; k++) {
            float s = warpSum(vals[k]);
            if (lane == 0) red[k][w] = s;
        }
        __syncthreads();
        if (t == 0) {
            #pragma unroll
            for (int k = 0; k < 5; k++) {
                float s = red[k][0] + red[k][1] + red[k][2] + red[k][3];
                g_rn[k * 4096 + r] = 1.0f / sqrtf(s);
            }
        }
    } else {
        int b = blockIdx.x - 4096;
        float guide = 0.f, sp = 0.f, ni = 0.f, nc = 0.f, nb = 0.f;
        for (int q = t; q < TT; q += 128) {
            float c  = cas[((size_t)b * TT + q) * 21 + 20];
            float a0 = att[((size_t)b * TT + q) * 3 + 0];
            float a1 = att[((size_t)b * TT + q) * 3 + 1];
            guide += fabsf(1.0f - c - a0);
            sp += a0 + a1;
        }
        for (int q = t; q < DD; q += 128) {
            float x;
            x = fi [b * DD + q]; ni += x * x;
            x = fc [b * DD + q]; nc += x * x;
            x = fbk[b * DD + q]; nb += x * x;
        }
        float vals[5] = {guide, sp, ni, nc, nb};
        #pragma unroll
        for (int k = 0; k < 5; k++) {
            float s = warpSum(vals[k]);
            if (lane == 0) red[k][w] = s;
        }
        __syncthreads();
        if (t == 0) {
            float s0=0,s1=0,s2=0,s3=0,s4=0;
            #pragma unroll
            for (int w2 = 0; w2 < 4; w2++) {
                s0 += red[0][w2]; s1 += red[1][w2]; s2 += red[2][w2];
                s3 += red[3][w2]; s4 += red[4][w2];
            }
            g_bstats[b*5+0] = s0;
            g_bstats[b*5+1] = s1;
            g_bstats[b*5+2] = sqrtf(s2);
            g_bstats[b*5+3] = sqrtf(s3);
            g_bstats[b*5+4] = sqrtf(s4);
        }
    }
}

// ---------------- 2) tf32 mma split-K GEMM (raw partials) ------------------
// 256 blocks x 128 threads, K=512 each, 2 blocks/SM.
#define SIM_STRIDE 36
#define SIM_TILE   (128 * SIM_STRIDE)
#define SIM_SMEM   (4 * SIM_TILE * 4)

__device__ __forceinline__ void cp16(float* smem_dst, const float* gsrc) {
    unsigned s = (unsigned)__cvta_generic_to_shared(smem_dst);
    asm volatile("cp.async.cg.shared.global [%0], [%1], 16;\n" :: "r"(s), "l"(gsrc));
}

__global__ void __launch_bounds__(128, 2)
sim_kernel(const float* __restrict__ lcs,
           const float* __restrict__ fa,
           const float* __restrict__ fb,
           const int* __restrict__ pos,
           const int* __restrict__ neg) {
    extern __shared__ float sh[];
    float* Abuf = sh;
    float* Bbuf = sh + 2 * SIM_TILE;

    int z = blockIdx.x;
    int t = threadIdx.x;
    int w = t >> 5, lane = t & 31;
    int wm = w >> 1, wn = w & 1;
    int lg = lane >> 2, lc = lane & 3;

    int p, koff, kind;
    if (z < 128)      { kind = 0; p = z >> 2;        koff = (z & 3) * 512; }
    else if (z < 192) { kind = 1; p = (z - 128) >> 1; koff = ((z - 128) & 1) * 512; }
    else              { kind = 2; p = (z - 192) >> 1; koff = 1024 + ((z - 192) & 1) * 512; }

    int ia, ib;
    if (p < 16) { ia = pos[2*p]; ib = pos[2*p+1]; }
    else        { ia = neg[2*(p-16)]; ib = neg[2*(p-16)+1]; }

    const float *abase, *bbase;
    if (kind == 0) {
        abase = lcs + (size_t)ia * LL * DD + koff;
        bbase = lcs + (size_t)ib * LL * DD + koff;
    } else {
        abase = fa + (size_t)ia * LL * DD + koff;
        bbase = ((p < 16) ? fa : fb) + (size_t)ib * LL * DD + koff;
    }
    float* out = g_S + (size_t)z * SLOT;

    float acc[4][8][4];
    #pragma unroll
    for (int mt = 0; mt < 4; mt++)
        #pragma unroll
        for (int nt = 0; nt < 8; nt++)
            #pragma unroll
            for (int j = 0; j < 4; j++) acc[mt][nt][j] = 0.f;

    #pragma unroll
    for (int u = 0; u < 8; u++) {
        int fq = u * 128 + t;
        int r = fq >> 3, cq = fq & 7;
        cp16(Abuf + r * SIM_STRIDE + cq * 4, abase + (size_t)r * DD + cq * 4);
        cp16(Bbuf + r * SIM_STRIDE + cq * 4, bbase + (size_t)r * DD + cq * 4);
    }
    asm volatile("cp.async.commit_group;\n");

    int buf = 0;
    for (int it = 0; it < 16; it++) {
        if (it + 1 < 16) {
            float* Ad = Abuf + (buf ^ 1) * SIM_TILE;
            float* Bd = Bbuf + (buf ^ 1) * SIM_TILE;
            int kt = (it + 1) * 32;
            #pragma unroll
            for (int u = 0; u < 8; u++) {
                int fq = u * 128 + t;
                int r = fq >> 3, cq = fq & 7;
                cp16(Ad + r * SIM_STRIDE + cq * 4, abase + (size_t)r * DD + kt + cq * 4);
                cp16(Bd + r * SIM_STRIDE + cq * 4, bbase + (size_t)r * DD + kt + cq * 4);
            }
        }
        asm volatile("cp.async.commit_group;\n");
        asm volatile("cp.async.wait_group 1;\n");
        __syncthreads();

        const float* As = Abuf + buf * SIM_TILE;
        const float* Bs = Bbuf + buf * SIM_TILE;
        #pragma unroll
        for (int ks = 0; ks < 4; ks++) {
            unsigned a[4][4], b[8][2];
            int c0 = ks * 8 + lc;
            #pragma unroll
            for (int mt = 0; mt < 4; mt++) {
                const float* base = As + (wm*64 + mt*16 + lg) * SIM_STRIDE + c0;
                a[mt][0] = __float_as_uint(base[0]);
                a[mt][1] = __float_as_uint(base[8 * SIM_STRIDE]);
                a[mt][2] = __float_as_uint(base[4]);
                a[mt][3] = __float_as_uint(base[8 * SIM_STRIDE + 4]);
            }
            #pragma unroll
            for (int nt = 0; nt < 8; nt++) {
                const float* base = Bs + (wn*64 + nt*8 + lg) * SIM_STRIDE + c0;
                b[nt][0] = __float_as_uint(base[0]);
                b[nt][1] = __float_as_uint(base[4]);
            }
            #pragma unroll
            for (int mt = 0; mt < 4; mt++)
                #pragma unroll
                for (int nt = 0; nt < 8; nt++)
                    asm volatile(
                        "mma.sync.aligned.m16n8k8.row.col.f32.tf32.tf32.f32 "
                        "{%0,%1,%2,%3}, {%4,%5,%6,%7}, {%8,%9}, {%0,%1,%2,%3};"
                        : "+f"(acc[mt][nt][0]), "+f"(acc[mt][nt][1]),
                          "+f"(acc[mt][nt][2]), "+f"(acc[mt][nt][3])
                        : "r"(a[mt][0]), "r"(a[mt][1]), "r"(a[mt][2]), "r"(a[mt][3]),
                          "r"(b[nt][0]), "r"(b[nt][1]));
        }
        __syncthreads();
        buf ^= 1;
    }

    // raw partial store (coalesced float2)
    #pragma unroll
    for (int mt = 0; mt < 4; mt++) {
        int row0 = wm*64 + mt*16 + lg;
        #pragma unroll
        for (int nt = 0; nt < 8; nt++) {
            int col0 = wn*64 + nt*8 + 2*lc;
            *(float2*)(out + row0 * 128 + col0) =
                make_float2(acc[mt][nt][0], acc[mt][nt][1]);
            *(float2*)(out + (row0 + 8) * 128 + col0) =
                make_float2(acc[mt][nt][2], acc[mt][nt][3]);
        }
    }
}

// ---------------- 3) wavefront DP + fused final ----------------
#define DP_STRIDE 130
#define DP_SMEM_BYTES ((2 * 128 * DP_STRIDE + 3 * 132) * 4)

__global__ void __launch_bounds__(128, 1)
dp_kernel(const int* __restrict__ pos, const int* __restrict__ neg,
          const float* __restrict__ xi, const float* __restrict__ xc,
          const float* __restrict__ xb, const float* __restrict__ vid,
          float* __restrict__ out) {
    extern __shared__ float sh[];
    float* Ms = sh;
    float* Gs = sh + 128 * DP_STRIDE;
    float* Pr = sh + 2 * 128 * DP_STRIDE;
    __shared__ bool isLast;

    int blk = blockIdx.x;
    int t = threadIdx.x;
    bool is_fsd = blk >= 32;
    int p = is_fsd ? blk - 32 : blk;
    int ia, ib;
    if (p < 16) { ia = pos[2*p]; ib = pos[2*p+1]; }
    else        { ia = neg[2*(p-16)]; ib = neg[2*(p-16)+1]; }

    if (!is_fsd) {
        const float* s0 = g_S + (size_t)(4*p + 0) * SLOT;
        const float* s1 = g_S + (size_t)(4*p + 1) * SLOT;
        const float* s2 = g_S + (size_t)(4*p + 2) * SLOT;
        const float* s3 = g_S + (size_t)(4*p + 3) * SLOT;
        const float* rnA = g_rn + ia * LL;
        float rbt = g_rn[ib * LL + t];
        for (int k = 0; k < 128; k++) {
            int q = k * 128 + t;
            float v = (s0[q] + s1[q] + s2[q] + s3[q]) * rnA[k] * rbt;
            Ms[k * DP_STRIDE + t] = fmaxf(0.f, (v - 0.8f) * 5.0f);
        }
    } else {
        const float* m0 = g_S + (size_t)(128 + 2*p) * SLOT;
        const float* m1 = g_S + (size_t)(128 + 2*p + 1) * SLOT;
        const float* g0 = g_S + (size_t)(192 + 2*p) * SLOT;
        const float* g1 = g_S + (size_t)(192 + 2*p + 1) * SLOT;
        const float* rnMA = g_rn + 1*4096 + ia * LL;
        const float* rnGA = g_rn + 2*4096 + ia * LL;
        float rMBt = g_rn[((p < 16) ? 1 : 3)*4096 + ib * LL + t];
        float rGBt = g_rn[((p < 16) ? 2 : 4)*4096 + ib * LL + t];
        for (int k = 0; k < 128; k++) {
            int q = k * 128 + t;
            Ms[k * DP_STRIDE + t] = (m0[q] + m1[q]) * rnMA[k] * rMBt;
            Gs[k * DP_STRIDE + t] = (g0[q] + g1[q]) * rnGA[k] * rGBt;
        }
    }
    for (int q = t; q < 3 * 132; q += 128) Pr[q] = 0.f;
    __syncthreads();

    float* P1 = Pr;
    float* P2 = Pr + 132;
    float* P0 = Pr + 264;

    const float S2L = 14.42695040888963f;    // 10 * log2(e)
    const float KLN = 0.06931471805599453f;  // 0.1 * ln(2)

    float cur = 0.f;
    int base = t * DP_STRIDE;

    for (int s = 0; s < 255; s++) {
        int j = s - t;
        bool act = ((unsigned)j < 128u);
        float up = P1[t];
        float dg = P2[t];
        float lf = cur;
        if (j == 0) { lf = 0.f; dg = 0.f; }
        if (act) {
            float nv;
            if (is_fsd) {
                float m = Ms[base + j];
                float g = Gs[base + j];
                float a0 = dg;
                float a1 = g + up;
                float a2 = g + lf;
                float m12 = fmaxf(a1, a2), n12 = fminf(a1, a2);
                float mx  = fmaxf(a0, m12), mn = fminf(a0, m12);
                float tt = -mx * S2L;
                float x1 = fmaf(mn,  S2L, tt);
                float x2 = fmaf(n12, S2L, tt);
                float e1, e2, lgv;
                asm("ex2.approx.ftz.f32 %0, %1;" : "=f"(e1) : "f"(x1));
                asm("ex2.approx.ftz.f32 %0, %1;" : "=f"(e2) : "f"(x2));
                float se = 1.0f + e1 + e2;
                asm("lg2.approx.ftz.f32 %0, %1;" : "=f"(lgv) : "f"(se));
                nv = fmaf(lgv, KLN, m + mx);
            } else {
                float m = Ms[base + j];
                nv = (m > 0.5f) ? (dg + m) : fmaxf(up, lf);
            }
            cur = nv;
            P0[t + 1] = nv;
        }
        __syncthreads();
        float* tmp = P2; P2 = P1; P1 = P0; P0 = tmp;
    }
    if (t == 127) g_dp[blk] = cur;

    // ---- last-block-done fused final ----
    __threadfence();
    __syncthreads();
    if (t == 0) {
        int c = atomicAdd(&g_ctr, 1);
        isLast = (c == 63);
    }
    __syncthreads();
    if (!isLast) return;
    if (t == 0) g_ctr = 0;

    if (t < 32) {
        int b = t;
        const float EPS = 1e-45f;
        float s = 0.f, li = 0.f, lcc = 0.f;
        #pragma unroll
        for (int c = 0; c < NC; c++) {
            float v = vid[b * NC + c];
            s += v;
            li  += __logf(xi[b * 21 + c] + EPS) * v;
            lcc += __logf(xc[b * 21 + c] + EPS) * v;
        }
        lcc += __logf(xc[b * 21 + 20] + EPS);
        float lb = __logf(xb[b * 21 + 20] + EPS);
        float cls_b = -(li / s) - (lcc / (s + 1.0f)) - lb;

        float guide = g_bstats[b*5+0];
        float sp    = g_bstats[b*5+1];
        float ni    = g_bstats[b*5+2];
        float nc2   = g_bstats[b*5+3];
        float nb    = g_bstats[b*5+4];
        float f1 = fmaxf(50.0f - ni + nc2, 0.f);
        float f2 = fmaxf(50.0f - nc2 + nb, 0.f);
        float fsum = f1 + f2 + nb;
        float feat_b = fsum * fsum;

        float lcs_v = g_dp[b];
        float fsd_v = g_dp[32 + b];
        float sign = (b < 16) ? -1.0f : 1.0f;

        float tot = cls_b * (1.0f / 32.0f)
                  + guide * (1.0f / 32.0f)
                  + 5e-5f * feat_b * (1.0f / 32.0f)
                  + 2e-4f * sp * (1.0f / 64.0f)
                  + 0.1f * sign * lcs_v * (1.0f / 16.0f)
                  + 0.1f * sign * fsd_v * (1.0f / 16.0f);

        tot = warpSum(tot);
        if (b == 0) out[0] = tot;
    }
}

// ---------------- launch ----------------
extern "C" void kernel_launch(void* const* d_in, const int* in_sizes, int n_in,
                              void* d_out, int out_size) {
    const float* xi   = (const float*)d_in[0];
    const float* xc   = (const float*)d_in[1];
    const float* xb   = (const float*)d_in[2];
    const float* vid  = (const float*)d_in[3];
    const float* att  = (const float*)d_in[4];
    const float* fi   = (const float*)d_in[5];
    const float* fc   = (const float*)d_in[6];
    const float* fbk  = (const float*)d_in[7];
    const float* cas  = (const float*)d_in[8];
    const float* lcs  = (const float*)d_in[9];
    const float* fa   = (const float*)d_in[10];
    const float* fb   = (const float*)d_in[11];
    const int*   pos  = (const int*)d_in[12];
    const int*   neg  = (const int*)d_in[13];
    float* out = (float*)d_out;

    cudaFuncSetAttribute(sim_kernel, cudaFuncAttributeMaxDynamicSharedMemorySize, SIM_SMEM);
    cudaFuncSetAttribute(dp_kernel, cudaFuncAttributeMaxDynamicSharedMemorySize, DP_SMEM_BYTES);

    prep_kernel<<<4128, 128>>>(lcs, fa, fb, att, cas, fi, fc, fbk);
    sim_kernel<<<256, 128, SIM_SMEM>>>(lcs, fa, fb, pos, neg);
    dp_kernel<<<64, 128, DP_SMEM_BYTES>>>(pos, neg, xi, xc, xb, vid, out);
}

// round 10
// speedup vs baseline: 2.9412x; 1.1311x over previous
#include <cuda_runtime.h>
#include <math.h>

#define LL 128
#define DD 2048
#define BSZ 32
#define TT 2048
#define NC 20
#define SLOT 16384

// ---------------- device scratch ----------------
// raw partial dot matrices, row-major 128x128:
// z 0..127  : LCS pair p=z>>2, K-quarter q=z&3 (koff=q*512)
// z 128..191: FSD-M pair p=(z-128)>>1, K-half h (koff=h*512)
// z 192..255: FSD-G pair p=(z-192)>>1, K-half h (koff=1024+h*512)
__device__ float g_S[256 * SLOT];
__device__ float g_rn[5 * 4096];     // 0 lcs, 1 act-m, 2 act-g, 3 bak-m, 4 bak-g
__device__ float g_bstats[BSZ * 5];
__device__ float g_dp[64];
__device__ int   g_ctr;

__device__ __forceinline__ float warpSum(float v) {
    #pragma unroll
    for (int o = 16; o > 0; o >>= 1) v += __shfl_down_sync(0xffffffffu, v, o);
    return v;
}

// ---------------- 1) warp-per-row norms + batch stats ----------------
// grid 544 x 256: blocks 0..511 norms (8 warps = 8 rows each), 512..543 bstats
__global__ void __launch_bounds__(256)
prep_kernel(const float* __restrict__ lcs,
            const float* __restrict__ fa,
            const float* __restrict__ fb,
            const float* __restrict__ att,
            const float* __restrict__ cas,
            const float* __restrict__ fi,
            const float* __restrict__ fc,
            const float* __restrict__ fbk) {
    int t = threadIdx.x;
    int w = t >> 5, lane = t & 31;

    if (blockIdx.x < 512) {
        int r = blockIdx.x * 8 + w;     // row 0..4095
        const float4* lrow = (const float4*)(lcs + (size_t)r * DD);
        const float4* arow = (const float4*)(fa  + (size_t)r * DD);
        const float4* brow = (const float4*)(fb  + (size_t)r * DD);
        float s_l = 0.f, s_am = 0.f, s_ag = 0.f, s_bm = 0.f, s_bg = 0.f;
        // 512 float4 per row, 32 lanes -> 16 iters; iters 0..7 = first half
        #pragma unroll 4
        for (int i = 0; i < 16; i++) {
            int q = i * 32 + lane;
            float4 v = lrow[q];
            s_l += v.x*v.x + v.y*v.y + v.z*v.z + v.w*v.w;
            float4 a = arow[q];
            float sa = a.x*a.x + a.y*a.y + a.z*a.z + a.w*a.w;
            float4 b = brow[q];
            float sb = b.x*b.x + b.y*b.y + b.z*b.z + b.w*b.w;
            if (i < 8) { s_am += sa; s_bm += sb; }
            else       { s_ag += sa; s_bg += sb; }
        }
        s_l  = warpSum(s_l);
        s_am = warpSum(s_am);
        s_ag = warpSum(s_ag);
        s_bm = warpSum(s_bm);
        s_bg = warpSum(s_bg);
        if (lane == 0) {
            g_rn[0 * 4096 + r] = 1.0f / sqrtf(s_l);
            g_rn[1 * 4096 + r] = 1.0f / sqrtf(s_am);
            g_rn[2 * 4096 + r] = 1.0f / sqrtf(s_ag);
            g_rn[3 * 4096 + r] = 1.0f / sqrtf(s_bm);
            g_rn[4 * 4096 + r] = 1.0f / sqrtf(s_bg);
        }
    } else {
        __shared__ float red[5][8];
        int b = blockIdx.x - 512;
        float guide = 0.f, sp = 0.f, ni = 0.f, nc = 0.f, nb = 0.f;
        for (int q = t; q < TT; q += 256) {
            float c  = cas[((size_t)b * TT + q) * 21 + 20];
            float a0 = att[((size_t)b * TT + q) * 3 + 0];
            float a1 = att[((size_t)b * TT + q) * 3 + 1];
            guide += fabsf(1.0f - c - a0);
            sp += a0 + a1;
        }
        for (int q = t; q < DD; q += 256) {
            float x;
            x = fi [b * DD + q]; ni += x * x;
            x = fc [b * DD + q]; nc += x * x;
            x = fbk[b * DD + q]; nb += x * x;
        }
        float vals[5] = {guide, sp, ni, nc, nb};
        #pragma unroll
        for (int k = 0; k < 5; k++) {
            float s = warpSum(vals[k]);
            if (lane == 0) red[k][w] = s;
        }
        __syncthreads();
        if (t == 0) {
            float s0=0,s1=0,s2=0,s3=0,s4=0;
            #pragma unroll
            for (int w2 = 0; w2 < 8; w2++) {
                s0 += red[0][w2]; s1 += red[1][w2]; s2 += red[2][w2];
                s3 += red[3][w2]; s4 += red[4][w2];
            }
            g_bstats[b*5+0] = s0;
            g_bstats[b*5+1] = s1;
            g_bstats[b*5+2] = sqrtf(s2);
            g_bstats[b*5+3] = sqrtf(s3);
            g_bstats[b*5+4] = sqrtf(s4);
        }
    }
}

// ---------------- 2) tf32 mma split-K GEMM (raw partials) ------------------
// 256 blocks x 128 threads, K=512 each, 2 blocks/SM.
#define SIM_STRIDE 36
#define SIM_TILE   (128 * SIM_STRIDE)
#define SIM_SMEM   (4 * SIM_TILE * 4)

__device__ __forceinline__ void cp16(float* smem_dst, const float* gsrc) {
    unsigned s = (unsigned)__cvta_generic_to_shared(smem_dst);
    asm volatile("cp.async.cg.shared.global [%0], [%1], 16;\n" :: "r"(s), "l"(gsrc));
}

__global__ void __launch_bounds__(128, 2)
sim_kernel(const float* __restrict__ lcs,
           const float* __restrict__ fa,
           const float* __restrict__ fb,
           const int* __restrict__ pos,
           const int* __restrict__ neg) {
    extern __shared__ float sh[];
    float* Abuf = sh;
    float* Bbuf = sh + 2 * SIM_TILE;

    int z = blockIdx.x;
    int t = threadIdx.x;
    int w = t >> 5, lane = t & 31;
    int wm = w >> 1, wn = w & 1;
    int lg = lane >> 2, lc = lane & 3;

    int p, koff, kind;
    if (z < 128)      { kind = 0; p = z >> 2;        koff = (z & 3) * 512; }
    else if (z < 192) { kind = 1; p = (z - 128) >> 1; koff = ((z - 128) & 1) * 512; }
    else              { kind = 2; p = (z - 192) >> 1; koff = 1024 + ((z - 192) & 1) * 512; }

    int ia, ib;
    if (p < 16) { ia = pos[2*p]; ib = pos[2*p+1]; }
    else        { ia = neg[2*(p-16)]; ib = neg[2*(p-16)+1]; }

    const float *abase, *bbase;
    if (kind == 0) {
        abase = lcs + (size_t)ia * LL * DD + koff;
        bbase = lcs + (size_t)ib * LL * DD + koff;
    } else {
        abase = fa + (size_t)ia * LL * DD + koff;
        bbase = ((p < 16) ? fa : fb) + (size_t)ib * LL * DD + koff;
    }
    float* out = g_S + (size_t)z * SLOT;

    float acc[4][8][4];
    #pragma unroll
    for (int mt = 0; mt < 4; mt++)
        #pragma unroll
        for (int nt = 0; nt < 8; nt++)
            #pragma unroll
            for (int j = 0; j < 4; j++) acc[mt][nt][j] = 0.f;

    #pragma unroll
    for (int u = 0; u < 8; u++) {
        int fq = u * 128 + t;
        int r = fq >> 3, cq = fq & 7;
        cp16(Abuf + r * SIM_STRIDE + cq * 4, abase + (size_t)r * DD + cq * 4);
        cp16(Bbuf + r * SIM_STRIDE + cq * 4, bbase + (size_t)r * DD + cq * 4);
    }
    asm volatile("cp.async.commit_group;\n");

    int buf = 0;
    for (int it = 0; it < 16; it++) {
        if (it + 1 < 16) {
            float* Ad = Abuf + (buf ^ 1) * SIM_TILE;
            float* Bd = Bbuf + (buf ^ 1) * SIM_TILE;
            int kt = (it + 1) * 32;
            #pragma unroll
            for (int u = 0; u < 8; u++) {
                int fq = u * 128 + t;
                int r = fq >> 3, cq = fq & 7;
                cp16(Ad + r * SIM_STRIDE + cq * 4, abase + (size_t)r * DD + kt + cq * 4);
                cp16(Bd + r * SIM_STRIDE + cq * 4, bbase + (size_t)r * DD + kt + cq * 4);
            }
        }
        asm volatile("cp.async.commit_group;\n");
        asm volatile("cp.async.wait_group 1;\n");
        __syncthreads();

        const float* As = Abuf + buf * SIM_TILE;
        const float* Bs = Bbuf + buf * SIM_TILE;
        #pragma unroll
        for (int ks = 0; ks < 4; ks++) {
            unsigned a[4][4], b[8][2];
            int c0 = ks * 8 + lc;
            #pragma unroll
            for (int mt = 0; mt < 4; mt++) {
                const float* base = As + (wm*64 + mt*16 + lg) * SIM_STRIDE + c0;
                a[mt][0] = __float_as_uint(base[0]);
                a[mt][1] = __float_as_uint(base[8 * SIM_STRIDE]);
                a[mt][2] = __float_as_uint(base[4]);
                a[mt][3] = __float_as_uint(base[8 * SIM_STRIDE + 4]);
            }
            #pragma unroll
            for (int nt = 0; nt < 8; nt++) {
                const float* base = Bs + (wn*64 + nt*8 + lg) * SIM_STRIDE + c0;
                b[nt][0] = __float_as_uint(base[0]);
                b[nt][1] = __float_as_uint(base[4]);
            }
            #pragma unroll
            for (int mt = 0; mt < 4; mt++)
                #pragma unroll
                for (int nt = 0; nt < 8; nt++)
                    asm volatile(
                        "mma.sync.aligned.m16n8k8.row.col.f32.tf32.tf32.f32 "
                        "{%0,%1,%2,%3}, {%4,%5,%6,%7}, {%8,%9}, {%0,%1,%2,%3};"
                        : "+f"(acc[mt][nt][0]), "+f"(acc[mt][nt][1]),
                          "+f"(acc[mt][nt][2]), "+f"(acc[mt][nt][3])
                        : "r"(a[mt][0]), "r"(a[mt][1]), "r"(a[mt][2]), "r"(a[mt][3]),
                          "r"(b[nt][0]), "r"(b[nt][1]));
        }
        __syncthreads();
        buf ^= 1;
    }

    // raw partial store (coalesced float2)
    #pragma unroll
    for (int mt = 0; mt < 4; mt++) {
        int row0 = wm*64 + mt*16 + lg;
        #pragma unroll
        for (int nt = 0; nt < 8; nt++) {
            int col0 = wn*64 + nt*8 + 2*lc;
            *(float2*)(out + row0 * 128 + col0) =
                make_float2(acc[mt][nt][0], acc[mt][nt][1]);
            *(float2*)(out + (row0 + 8) * 128 + col0) =
                make_float2(acc[mt][nt][2], acc[mt][nt][3]);
        }
    }
}

// ---------------- 3) wavefront DP + fused final ----------------
#define DP_STRIDE 130
#define DP_SMEM_BYTES ((2 * 128 * DP_STRIDE + 3 * 132) * 4)

__global__ void __launch_bounds__(128, 1)
dp_kernel(const int* __restrict__ pos, const int* __restrict__ neg,
          const float* __restrict__ xi, const float* __restrict__ xc,
          const float* __restrict__ xb, const float* __restrict__ vid,
          float* __restrict__ out) {
    extern __shared__ float sh[];
    float* Ms = sh;
    float* Gs = sh + 128 * DP_STRIDE;
    float* Pr = sh + 2 * 128 * DP_STRIDE;
    __shared__ bool isLast;

    int blk = blockIdx.x;
    int t = threadIdx.x;
    bool is_fsd = blk >= 32;
    int p = is_fsd ? blk - 32 : blk;
    int ia, ib;
    if (p < 16) { ia = pos[2*p]; ib = pos[2*p+1]; }
    else        { ia = neg[2*(p-16)]; ib = neg[2*(p-16)+1]; }

    if (!is_fsd) {
        const float* s0 = g_S + (size_t)(4*p + 0) * SLOT;
        const float* s1 = g_S + (size_t)(4*p + 1) * SLOT;
        const float* s2 = g_S + (size_t)(4*p + 2) * SLOT;
        const float* s3 = g_S + (size_t)(4*p + 3) * SLOT;
        const float* rnA = g_rn + ia * LL;
        float rbt = g_rn[ib * LL + t];
        for (int k = 0; k < 128; k++) {
            int q = k * 128 + t;
            float v = (s0[q] + s1[q] + s2[q] + s3[q]) * rnA[k] * rbt;
            Ms[k * DP_STRIDE + t] = fmaxf(0.f, (v - 0.8f) * 5.0f);
        }
    } else {
        const float* m0 = g_S + (size_t)(128 + 2*p) * SLOT;
        const float* m1 = g_S + (size_t)(128 + 2*p + 1) * SLOT;
        const float* g0 = g_S + (size_t)(192 + 2*p) * SLOT;
        const float* g1 = g_S + (size_t)(192 + 2*p + 1) * SLOT;
        const float* rnMA = g_rn + 1*4096 + ia * LL;
        const float* rnGA = g_rn + 2*4096 + ia * LL;
        float rMBt = g_rn[((p < 16) ? 1 : 3)*4096 + ib * LL + t];
        float rGBt = g_rn[((p < 16) ? 2 : 4)*4096 + ib * LL + t];
        for (int k = 0; k < 128; k++) {
            int q = k * 128 + t;
            Ms[k * DP_STRIDE + t] = (m0[q] + m1[q]) * rnMA[k] * rMBt;
            Gs[k * DP_STRIDE + t] = (g0[q] + g1[q]) * rnGA[k] * rGBt;
        }
    }
    for (int q = t; q < 3 * 132; q += 128) Pr[q] = 0.f;
    __syncthreads();

    float* P1 = Pr;
    float* P2 = Pr + 132;
    float* P0 = Pr + 264;

    const float S2L = 14.42695040888963f;    // 10 * log2(e)
    const float KLN = 0.06931471805599453f;  // 0.1 * ln(2)

    float cur = 0.f;
    int base = t * DP_STRIDE;

    for (int s = 0; s < 255; s++) {
        int j = s - t;
        bool act = ((unsigned)j < 128u);
        float up = P1[t];
        float dg = P2[t];
        float lf = cur;
        if (j == 0) { lf = 0.f; dg = 0.f; }
        if (act) {
            float nv;
            if (is_fsd) {
                float m = Ms[base + j];
                float g = Gs[base + j];
                float a0 = dg;
                float a1 = g + up;
                float a2 = g + lf;
                float m12 = fmaxf(a1, a2), n12 = fminf(a1, a2);
                float mx  = fmaxf(a0, m12), mn = fminf(a0, m12);
                float tt = -mx * S2L;
                float x1 = fmaf(mn,  S2L, tt);
                float x2 = fmaf(n12, S2L, tt);
                float e1, e2, lgv;
                asm("ex2.approx.ftz.f32 %0, %1;" : "=f"(e1) : "f"(x1));
                asm("ex2.approx.ftz.f32 %0, %1;" : "=f"(e2) : "f"(x2));
                float se = 1.0f + e1 + e2;
                asm("lg2.approx.ftz.f32 %0, %1;" : "=f"(lgv) : "f"(se));
                nv = fmaf(lgv, KLN, m + mx);
            } else {
                float m = Ms[base + j];
                nv = (m > 0.5f) ? (dg + m) : fmaxf(up, lf);
            }
            cur = nv;
            P0[t + 1] = nv;
        }
        __syncthreads();
        float* tmp = P2; P2 = P1; P1 = P0; P0 = tmp;
    }
    if (t == 127) g_dp[blk] = cur;

    // ---- last-block-done fused final ----
    __threadfence();
    __syncthreads();
    if (t == 0) {
        int c = atomicAdd(&g_ctr, 1);
        isLast = (c == 63);
    }
    __syncthreads();
    if (!isLast) return;
    if (t == 0) g_ctr = 0;

    if (t < 32) {
        int b = t;
        const float EPS = 1e-45f;
        float s = 0.f, li = 0.f, lcc = 0.f;
        #pragma unroll
        for (int c = 0; c < NC; c++) {
            float v = vid[b * NC + c];
            s += v;
            li  += __logf(xi[b * 21 + c] + EPS) * v;
            lcc += __logf(xc[b * 21 + c] + EPS) * v;
        }
        lcc += __logf(xc[b * 21 + 20] + EPS);
        float lb = __logf(xb[b * 21 + 20] + EPS);
        float cls_b = -(li / s) - (lcc / (s + 1.0f)) - lb;

        float guide = g_bstats[b*5+0];
        float sp    = g_bstats[b*5+1];
        float ni    = g_bstats[b*5+2];
        float nc2   = g_bstats[b*5+3];
        float nb    = g_bstats[b*5+4];
        float f1 = fmaxf(50.0f - ni + nc2, 0.f);
        float f2 = fmaxf(50.0f - nc2 + nb, 0.f);
        float fsum = f1 + f2 + nb;
        float feat_b = fsum * fsum;

        float lcs_v = g_dp[b];
        float fsd_v = g_dp[32 + b];
        float sign = (b < 16) ? -1.0f : 1.0f;

        float tot = cls_b * (1.0f / 32.0f)
                  + guide * (1.0f / 32.0f)
                  + 5e-5f * feat_b * (1.0f / 32.0f)
                  + 2e-4f * sp * (1.0f / 64.0f)
                  + 0.1f * sign * lcs_v * (1.0f / 16.0f)
                  + 0.1f * sign * fsd_v * (1.0f / 16.0f);

        tot = warpSum(tot);
        if (b == 0) out[0] = tot;
    }
}

// ---------------- launch ----------------
extern "C" void kernel_launch(void* const* d_in, const int* in_sizes, int n_in,
                              void* d_out, int out_size) {
    const float* xi   = (const float*)d_in[0];
    const float* xc   = (const float*)d_in[1];
    const float* xb   = (const float*)d_in[2];
    const float* vid  = (const float*)d_in[3];
    const float* att  = (const float*)d_in[4];
    const float* fi   = (const float*)d_in[5];
    const float* fc   = (const float*)d_in[6];
    const float* fbk  = (const float*)d_in[7];
    const float* cas  = (const float*)d_in[8];
    const float* lcs  = (const float*)d_in[9];
    const float* fa   = (const float*)d_in[10];
    const float* fb   = (const float*)d_in[11];
    const int*   pos  = (const int*)d_in[12];
    const int*   neg  = (const int*)d_in[13];
    float* out = (float*)d_out;

    cudaFuncSetAttribute(sim_kernel, cudaFuncAttributeMaxDynamicSharedMemorySize, SIM_SMEM);
    cudaFuncSetAttribute(dp_kernel, cudaFuncAttributeMaxDynamicSharedMemorySize, DP_SMEM_BYTES);

    prep_kernel<<<544, 256>>>(lcs, fa, fb, att, cas, fi, fc, fbk);
    sim_kernel<<<256, 128, SIM_SMEM>>>(lcs, fa, fb, pos, neg);
    dp_kernel<<<64, 128, DP_SMEM_BYTES>>>(pos, neg, xi, xc, xb, vid, out);
}

// round 12
// speedup vs baseline: 3.1509x; 1.0713x over previous
#include <cuda_runtime.h>
#include <math.h>

#define LL 128
#define DD 2048
#define BSZ 32
#define TT 2048
#define NC 20
#define SLOT 16384

// ---------------- device scratch ----------------
// raw partial dot matrices, row-major 128x128:
// z 0..127  : LCS pair p=z>>2, K-quarter q=z&3 (koff=q*512)
// z 128..191: FSD-M pair p=(z-128)>>1, K-half h (koff=h*512)
// z 192..255: FSD-G pair p=(z-192)>>1, K-half h (koff=1024+h*512)
__device__ float g_S[256 * SLOT];
__device__ float g_rn[5 * 4096];     // 0 lcs, 1 act-m, 2 act-g, 3 bak-m, 4 bak-g
__device__ float g_bstats[BSZ * 5];
__device__ float g_dp[64];
__device__ int   g_ctr;

__device__ __forceinline__ float warpSum(float v) {
    #pragma unroll
    for (int o = 16; o > 0; o >>= 1) v += __shfl_down_sync(0xffffffffu, v, o);
    return v;
}

// ---------------- 1) warp-per-row norms + batch stats ----------------
__global__ void __launch_bounds__(256)
prep_kernel(const float* __restrict__ lcs,
            const float* __restrict__ fa,
            const float* __restrict__ fb,
            const float* __restrict__ att,
            const float* __restrict__ cas,
            const float* __restrict__ fi,
            const float* __restrict__ fc,
            const float* __restrict__ fbk) {
    int t = threadIdx.x;
    int w = t >> 5, lane = t & 31;

    if (blockIdx.x < 512) {
        int r = blockIdx.x * 8 + w;     // row 0..4095
        const float4* lrow = (const float4*)(lcs + (size_t)r * DD);
        const float4* arow = (const float4*)(fa  + (size_t)r * DD);
        const float4* brow = (const float4*)(fb  + (size_t)r * DD);
        float s_l = 0.f, s_am = 0.f, s_ag = 0.f, s_bm = 0.f, s_bg = 0.f;
        #pragma unroll 4
        for (int i = 0; i < 16; i++) {
            int q = i * 32 + lane;
            float4 v = lrow[q];
            s_l += v.x*v.x + v.y*v.y + v.z*v.z + v.w*v.w;
            float4 a = arow[q];
            float sa = a.x*a.x + a.y*a.y + a.z*a.z + a.w*a.w;
            float4 b = brow[q];
            float sb = b.x*b.x + b.y*b.y + b.z*b.z + b.w*b.w;
            if (i < 8) { s_am += sa; s_bm += sb; }
            else       { s_ag += sa; s_bg += sb; }
        }
        s_l  = warpSum(s_l);
        s_am = warpSum(s_am);
        s_ag = warpSum(s_ag);
        s_bm = warpSum(s_bm);
        s_bg = warpSum(s_bg);
        if (lane == 0) {
            g_rn[0 * 4096 + r] = 1.0f / sqrtf(s_l);
            g_rn[1 * 4096 + r] = 1.0f / sqrtf(s_am);
            g_rn[2 * 4096 + r] = 1.0f / sqrtf(s_ag);
            g_rn[3 * 4096 + r] = 1.0f / sqrtf(s_bm);
            g_rn[4 * 4096 + r] = 1.0f / sqrtf(s_bg);
        }
    } else {
        __shared__ float red[5][8];
        int b = blockIdx.x - 512;
        float guide = 0.f, sp = 0.f, ni = 0.f, nc = 0.f, nb = 0.f;
        for (int q = t; q < TT; q += 256) {
            float c  = cas[((size_t)b * TT + q) * 21 + 20];
            float a0 = att[((size_t)b * TT + q) * 3 + 0];
            float a1 = att[((size_t)b * TT + q) * 3 + 1];
            guide += fabsf(1.0f - c - a0);
            sp += a0 + a1;
        }
        for (int q = t; q < DD; q += 256) {
            float x;
            x = fi [b * DD + q]; ni += x * x;
            x = fc [b * DD + q]; nc += x * x;
            x = fbk[b * DD + q]; nb += x * x;
        }
        float vals[5] = {guide, sp, ni, nc, nb};
        #pragma unroll
        for (int k = 0; k < 5; k++) {
            float s = warpSum(vals[k]);
            if (lane == 0) red[k][w] = s;
        }
        __syncthreads();
        if (t == 0) {
            float s0=0,s1=0,s2=0,s3=0,s4=0;
            #pragma unroll
            for (int w2 = 0; w2 < 8; w2++) {
                s0 += red[0][w2]; s1 += red[1][w2]; s2 += red[2][w2];
                s3 += red[3][w2]; s4 += red[4][w2];
            }
            g_bstats[b*5+0] = s0;
            g_bstats[b*5+1] = s1;
            g_bstats[b*5+2] = sqrtf(s2);
            g_bstats[b*5+3] = sqrtf(s3);
            g_bstats[b*5+4] = sqrtf(s4);
        }
    }
}

// ---------------- 2) tf32 mma split-K GEMM (raw partials) ------------------
#define SIM_STRIDE 36
#define SIM_TILE   (128 * SIM_STRIDE)
#define SIM_SMEM   (4 * SIM_TILE * 4)

__device__ __forceinline__ void cp16(float* smem_dst, const float* gsrc) {
    unsigned s = (unsigned)__cvta_generic_to_shared(smem_dst);
    asm volatile("cp.async.cg.shared.global [%0], [%1], 16;\n" :: "r"(s), "l"(gsrc));
}

__global__ void __launch_bounds__(128, 2)
sim_kernel(const float* __restrict__ lcs,
           const float* __restrict__ fa,
           const float* __restrict__ fb,
           const int* __restrict__ pos,
           const int* __restrict__ neg) {
    extern __shared__ float sh[];
    float* Abuf = sh;
    float* Bbuf = sh + 2 * SIM_TILE;

    int z = blockIdx.x;
    int t = threadIdx.x;
    int w = t >> 5, lane = t & 31;
    int wm = w >> 1, wn = w & 1;
    int lg = lane >> 2, lc = lane & 3;

    int p, koff, kind;
    if (z < 128)      { kind = 0; p = z >> 2;        koff = (z & 3) * 512; }
    else if (z < 192) { kind = 1; p = (z - 128) >> 1; koff = ((z - 128) & 1) * 512; }
    else              { kind = 2; p = (z - 192) >> 1; koff = 1024 + ((z - 192) & 1) * 512; }

    int ia, ib;
    if (p < 16) { ia = pos[2*p]; ib = pos[2*p+1]; }
    else        { ia = neg[2*(p-16)]; ib = neg[2*(p-16)+1]; }

    const float *abase, *bbase;
    if (kind == 0) {
        abase = lcs + (size_t)ia * LL * DD + koff;
        bbase = lcs + (size_t)ib * LL * DD + koff;
    } else {
        abase = fa + (size_t)ia * LL * DD + koff;
        bbase = ((p < 16) ? fa : fb) + (size_t)ib * LL * DD + koff;
    }
    float* out = g_S + (size_t)z * SLOT;

    float acc[4][8][4];
    #pragma unroll
    for (int mt = 0; mt < 4; mt++)
        #pragma unroll
        for (int nt = 0; nt < 8; nt++)
            #pragma unroll
            for (int j = 0; j < 4; j++) acc[mt][nt][j] = 0.f;

    #pragma unroll
    for (int u = 0; u < 8; u++) {
        int fq = u * 128 + t;
        int r = fq >> 3, cq = fq & 7;
        cp16(Abuf + r * SIM_STRIDE + cq * 4, abase + (size_t)r * DD + cq * 4);
        cp16(Bbuf + r * SIM_STRIDE + cq * 4, bbase + (size_t)r * DD + cq * 4);
    }
    asm volatile("cp.async.commit_group;\n");

    int buf = 0;
    for (int it = 0; it < 16; it++) {
        if (it + 1 < 16) {
            float* Ad = Abuf + (buf ^ 1) * SIM_TILE;
            float* Bd = Bbuf + (buf ^ 1) * SIM_TILE;
            int kt = (it + 1) * 32;
            #pragma unroll
            for (int u = 0; u < 8; u++) {
                int fq = u * 128 + t;
                int r = fq >> 3, cq = fq & 7;
                cp16(Ad + r * SIM_STRIDE + cq * 4, abase + (size_t)r * DD + kt + cq * 4);
                cp16(Bd + r * SIM_STRIDE + cq * 4, bbase + (size_t)r * DD + kt + cq * 4);
            }
        }
        asm volatile("cp.async.commit_group;\n");
        asm volatile("cp.async.wait_group 1;\n");
        __syncthreads();

        const float* As = Abuf + buf * SIM_TILE;
        const float* Bs = Bbuf + buf * SIM_TILE;
        #pragma unroll
        for (int ks = 0; ks < 4; ks++) {
            unsigned a[4][4], b[8][2];
            int c0 = ks * 8 + lc;
            #pragma unroll
            for (int mt = 0; mt < 4; mt++) {
                const float* base = As + (wm*64 + mt*16 + lg) * SIM_STRIDE + c0;
                a[mt][0] = __float_as_uint(base[0]);
                a[mt][1] = __float_as_uint(base[8 * SIM_STRIDE]);
                a[mt][2] = __float_as_uint(base[4]);
                a[mt][3] = __float_as_uint(base[8 * SIM_STRIDE + 4]);
            }
            #pragma unroll
            for (int nt = 0; nt < 8; nt++) {
                const float* base = Bs + (wn*64 + nt*8 + lg) * SIM_STRIDE + c0;
                b[nt][0] = __float_as_uint(base[0]);
                b[nt][1] = __float_as_uint(base[4]);
            }
            #pragma unroll
            for (int mt = 0; mt < 4; mt++)
                #pragma unroll
                for (int nt = 0; nt < 8; nt++)
                    asm volatile(
                        "mma.sync.aligned.m16n8k8.row.col.f32.tf32.tf32.f32 "
                        "{%0,%1,%2,%3}, {%4,%5,%6,%7}, {%8,%9}, {%0,%1,%2,%3};"
                        : "+f"(acc[mt][nt][0]), "+f"(acc[mt][nt][1]),
                          "+f"(acc[mt][nt][2]), "+f"(acc[mt][nt][3])
                        : "r"(a[mt][0]), "r"(a[mt][1]), "r"(a[mt][2]), "r"(a[mt][3]),
                          "r"(b[nt][0]), "r"(b[nt][1]));
        }
        __syncthreads();
        buf ^= 1;
    }

    #pragma unroll
    for (int mt = 0; mt < 4; mt++) {
        int row0 = wm*64 + mt*16 + lg;
        #pragma unroll
        for (int nt = 0; nt < 8; nt++) {
            int col0 = wn*64 + nt*8 + 2*lc;
            *(float2*)(out + row0 * 128 + col0) =
                make_float2(acc[mt][nt][0], acc[mt][nt][1]);
            *(float2*)(out + (row0 + 8) * 128 + col0) =
                make_float2(acc[mt][nt][2], acc[mt][nt][3]);
        }
    }
}

// ---------------- 3) wavefront DP + fused final ----------------
#define DP_STRIDE 130
#define DP_SMEM_BYTES ((2 * 128 * DP_STRIDE + 3 * 132) * 4)

__global__ void __launch_bounds__(128, 1)
dp_kernel(const int* __restrict__ pos, const int* __restrict__ neg,
          const float* __restrict__ xi, const float* __restrict__ xc,
          const float* __restrict__ xb, const float* __restrict__ vid,
          float* __restrict__ out) {
    extern __shared__ float sh[];
    float* Ms = sh;
    float* Gs = sh + 128 * DP_STRIDE;
    float* Pr = sh + 2 * 128 * DP_STRIDE;
    __shared__ bool isLast;

    int blk = blockIdx.x;
    int t = threadIdx.x;
    bool is_fsd = blk >= 32;
    int p = is_fsd ? blk - 32 : blk;
    int ia, ib;
    if (p < 16) { ia = pos[2*p]; ib = pos[2*p+1]; }
    else        { ia = neg[2*(p-16)]; ib = neg[2*(p-16)+1]; }

    if (!is_fsd) {
        const float* s0 = g_S + (size_t)(4*p + 0) * SLOT;
        const float* s1 = g_S + (size_t)(4*p + 1) * SLOT;
        const float* s2 = g_S + (size_t)(4*p + 2) * SLOT;
        const float* s3 = g_S + (size_t)(4*p + 3) * SLOT;
        const float* rnA = g_rn + ia * LL;
        float rbt = g_rn[ib * LL + t];
        for (int k = 0; k < 128; k++) {
            int q = k * 128 + t;
            float v = (s0[q] + s1[q] + s2[q] + s3[q]) * rnA[k] * rbt;
            Ms[k * DP_STRIDE + t] = fmaxf(0.f, (v - 0.8f) * 5.0f);
        }
    } else {
        const float* m0 = g_S + (size_t)(128 + 2*p) * SLOT;
        const float* m1 = g_S + (size_t)(128 + 2*p + 1) * SLOT;
        const float* g0 = g_S + (size_t)(192 + 2*p) * SLOT;
        const float* g1 = g_S + (size_t)(192 + 2*p + 1) * SLOT;
        const float* rnMA = g_rn + 1*4096 + ia * LL;
        const float* rnGA = g_rn + 2*4096 + ia * LL;
        float rMBt = g_rn[((p < 16) ? 1 : 3)*4096 + ib * LL + t];
        float rGBt = g_rn[((p < 16) ? 2 : 4)*4096 + ib * LL + t];
        for (int k = 0; k < 128; k++) {
            int q = k * 128 + t;
            Ms[k * DP_STRIDE + t] = (m0[q] + m1[q]) * rnMA[k] * rMBt;
            Gs[k * DP_STRIDE + t] = (g0[q] + g1[q]) * rnGA[k] * rGBt;
        }
    }
    for (int q = t; q < 3 * 132; q += 128) Pr[q] = 0.f;
    __syncthreads();

    float* P1 = Pr;
    float* P2 = Pr + 132;
    float* P0 = Pr + 264;

    const float S2L = 14.42695040888963f;    // 10 * log2(e)
    const float KLN = 0.06931471805599453f;  // 0.1 * ln(2)

    float cur = 0.f;
    int base = t * DP_STRIDE;

    for (int s = 0; s < 255; s++) {
        int j = s - t;
        bool act = ((unsigned)j < 128u);
        float up = P1[t];
        float dg = P2[t];
        float lf = cur;
        if (j == 0) { lf = 0.f; dg = 0.f; }
        if (act) {
            float nv;
            if (is_fsd) {
                float m = Ms[base + j];
                float g = Gs[base + j];
                float a0 = dg;
                float a1 = g + up;
                float a2 = g + lf;
                float m12 = fmaxf(a1, a2), n12 = fminf(a1, a2);
                float mx  = fmaxf(a0, m12), mn = fminf(a0, m12);
                float tt = -mx * S2L;
                float x1 = fmaf(mn,  S2L, tt);
                float x2 = fmaf(n12, S2L, tt);
                float e1, e2, lgv;
                asm("ex2.approx.ftz.f32 %0, %1;" : "=f"(e1) : "f"(x1));
                asm("ex2.approx.ftz.f32 %0, %1;" : "=f"(e2) : "f"(x2));
                float se = 1.0f + e1 + e2;
                asm("lg2.approx.ftz.f32 %0, %1;" : "=f"(lgv) : "f"(se));
                nv = fmaf(lgv, KLN, m + mx);
            } else {
                float m = Ms[base + j];
                nv = (m > 0.5f) ? (dg + m) : fmaxf(up, lf);
            }
            cur = nv;
            P0[t + 1] = nv;
        }
        __syncthreads();
        float* tmp = P2; P2 = P1; P1 = P0; P0 = tmp;
    }
    if (t == 127) g_dp[blk] = cur;

    // ---- last-block-done fused final ----
    __threadfence();
    __syncthreads();
    if (t == 0) {
        int c = atomicAdd(&g_ctr, 1);
        isLast = (c == 63);
    }
    __syncthreads();
    if (!isLast) return;
    if (t == 0) g_ctr = 0;

    if (t < 32) {
        int b = t;
        const float EPS = 1e-45f;
        float s = 0.f, li = 0.f, lcc = 0.f;
        #pragma unroll
        for (int c = 0; c < NC; c++) {
            float v = vid[b * NC + c];
            s += v;
            li  += __logf(xi[b * 21 + c] + EPS) * v;
            lcc += __logf(xc[b * 21 + c] + EPS) * v;
        }
        lcc += __logf(xc[b * 21 + 20] + EPS);
        float lb = __logf(xb[b * 21 + 20] + EPS);
        float cls_b = -(li / s) - (lcc / (s + 1.0f)) - lb;

        float guide = g_bstats[b*5+0];
        float sp    = g_bstats[b*5+1];
        float ni    = g_bstats[b*5+2];
        float nc2   = g_bstats[b*5+3];
        float nb    = g_bstats[b*5+4];
        float f1 = fmaxf(50.0f - ni + nc2, 0.f);
        float f2 = fmaxf(50.0f - nc2 + nb, 0.f);
        float fsum = f1 + f2 + nb;
        float feat_b = fsum * fsum;

        float lcs_v = g_dp[b];
        float fsd_v = g_dp[32 + b];
        float sign = (b < 16) ? -1.0f : 1.0f;

        float tot = cls_b * (1.0f / 32.0f)
                  + guide * (1.0f / 32.0f)
                  + 5e-5f * feat_b * (1.0f / 32.0f)
                  + 2e-4f * sp * (1.0f / 64.0f)
                  + 0.1f * sign * lcs_v * (1.0f / 16.0f)
                  + 0.1f * sign * fsd_v * (1.0f / 16.0f);

        tot = warpSum(tot);
        if (b == 0) out[0] = tot;
    }
}

// ---------------- launch ----------------
extern "C" void kernel_launch(void* const* d_in, const int* in_sizes, int n_in,
                              void* d_out, int out_size) {
    const float* xi   = (const float*)d_in[0];
    const float* xc   = (const float*)d_in[1];
    const float* xb   = (const float*)d_in[2];
    const float* vid  = (const float*)d_in[3];
    const float* att  = (const float*)d_in[4];
    const float* fi   = (const float*)d_in[5];
    const float* fc   = (const float*)d_in[6];
    const float* fbk  = (const float*)d_in[7];
    const float* cas  = (const float*)d_in[8];
    const float* lcs  = (const float*)d_in[9];
    const float* fa   = (const float*)d_in[10];
    const float* fb   = (const float*)d_in[11];
    const int*   pos  = (const int*)d_in[12];
    const int*   neg  = (const int*)d_in[13];
    float* out = (float*)d_out;

    // One-time resource init (first call is the uncaptured correctness run).
    // Every call enqueues IDENTICAL work; only stream/event handles persist.
    static cudaStream_t s2 = nullptr;
    static cudaEvent_t ev0 = nullptr, ev1 = nullptr;
    if (s2 == nullptr) {
        cudaStreamCreate(&s2);
        cudaEventCreateWithFlags(&ev0, cudaEventDisableTiming);
        cudaEventCreateWithFlags(&ev1, cudaEventDisableTiming);
        cudaFuncSetAttribute(sim_kernel, cudaFuncAttributeMaxDynamicSharedMemorySize, SIM_SMEM);
        cudaFuncSetAttribute(dp_kernel, cudaFuncAttributeMaxDynamicSharedMemorySize, DP_SMEM_BYTES);
    }

    // Fork: sim (stream s2) runs concurrently with prep (default stream).
    cudaEventRecord(ev0, 0);
    cudaStreamWaitEvent(s2, ev0, 0);
    sim_kernel<<<256, 128, SIM_SMEM, s2>>>(lcs, fa, fb, pos, neg);
    cudaEventRecord(ev1, s2);

    prep_kernel<<<544, 256>>>(lcs, fa, fb, att, cas, fi, fc, fbk);

    // Join: dp needs both sim partials and prep norms.
    cudaStreamWaitEvent(0, ev1, 0);
    dp_kernel<<<64, 128, DP_SMEM_BYTES>>>(pos, neg, xi, xc, xb, vid, out);
}